// round 5
// baseline (speedup 1.0000x reference)
#include <cuda_runtime.h>
#include <cuda_fp16.h>
#include <math.h>
#include <stddef.h>
#include <stdint.h>

// Problem dims (fixed by the reference)
#define T_DIM 4096
#define H_DIM 2048
#define K_DIM 1024
#define V_DIM 1024
#define O_DIM 2048

// fp32 scratch: q[T*K] | k[T*K] | g[T*K] | v[T*V] | opre[T*V] | state_dump[K*V]
__device__ __align__(16) float g_scratch[(size_t)3 * T_DIM * K_DIM +
                                         (size_t)2 * T_DIM * V_DIM +
                                         (size_t)K_DIM * V_DIM];
// fp16 scratch: Xh[T*H] | Wqh | Wkh | Wgh | Wvh (K*H each) | Woh[O*V] | opreh[T*V]
__device__ __align__(16) __half g_scratch_h[(size_t)T_DIM * H_DIM +
                                            (size_t)4 * K_DIM * H_DIM +
                                            (size_t)O_DIM * V_DIM +
                                            (size_t)T_DIM * V_DIM];

// ---------------------------------------------------------------------------
// Packed fp32x2 helpers (sm_100+)
// ---------------------------------------------------------------------------
__device__ __forceinline__ unsigned long long pk2(float lo, float hi) {
    unsigned long long r;
    asm("mov.b64 %0, {%1, %2};" : "=l"(r) : "f"(lo), "f"(hi));
    return r;
}
__device__ __forceinline__ void upk2(unsigned long long v, float& lo, float& hi) {
    asm("mov.b64 {%0, %1}, %2;" : "=f"(lo), "=f"(hi) : "l"(v));
}
__device__ __forceinline__ unsigned long long fma2(unsigned long long a,
                                                   unsigned long long b,
                                                   unsigned long long c) {
    unsigned long long d;
    asm("fma.rn.f32x2 %0, %1, %2, %3;" : "=l"(d) : "l"(a), "l"(b), "l"(c));
    return d;
}
__device__ __forceinline__ unsigned long long mul2(unsigned long long a,
                                                   unsigned long long b) {
    unsigned long long d;
    asm("mul.rn.f32x2 %0, %1, %2;" : "=l"(d) : "l"(a), "l"(b));
    return d;
}

// ---------------------------------------------------------------------------
// Tensor-core + cp.async helpers
// ---------------------------------------------------------------------------
__device__ __forceinline__ void ldm_x4(uint32_t* r, const __half* p) {
    uint32_t addr = (uint32_t)__cvta_generic_to_shared(p);
    asm volatile("ldmatrix.sync.aligned.m8n8.x4.shared.b16 {%0,%1,%2,%3}, [%4];"
                 : "=r"(r[0]), "=r"(r[1]), "=r"(r[2]), "=r"(r[3])
                 : "r"(addr));
}
__device__ __forceinline__ void mma16816(float* d, const uint32_t* a, const uint32_t* b) {
    asm volatile(
        "mma.sync.aligned.m16n8k16.row.col.f32.f16.f16.f32 "
        "{%0,%1,%2,%3}, {%4,%5,%6,%7}, {%8,%9}, {%0,%1,%2,%3};"
        : "+f"(d[0]), "+f"(d[1]), "+f"(d[2]), "+f"(d[3])
        : "r"(a[0]), "r"(a[1]), "r"(a[2]), "r"(a[3]), "r"(b[0]), "r"(b[1]));
}
__device__ __forceinline__ void cp_async16(__half* smem_dst, const __half* gsrc) {
    uint32_t d = (uint32_t)__cvta_generic_to_shared(smem_dst);
    asm volatile("cp.async.cg.shared.global [%0], [%1], 16;" :: "r"(d), "l"(gsrc));
}
#define CP_COMMIT() asm volatile("cp.async.commit_group;")
#define CP_WAIT(n)  asm volatile("cp.async.wait_group %0;" :: "n"(n))

// ---------------------------------------------------------------------------
// fp32 -> fp16 convert, vectorized (float4 in, 4x half = 8B out)
// ---------------------------------------------------------------------------
__global__ void f2h_kernel(const float* __restrict__ src, __half* __restrict__ dst,
                           int n4)
{
    int i = blockIdx.x * blockDim.x + threadIdx.x;
    const int stride = gridDim.x * blockDim.x;
    for (; i < n4; i += stride) {
        float4 v = ((const float4*)src)[i];
        __half2 h0 = __floats2half2_rn(v.x, v.y);
        __half2 h1 = __floats2half2_rn(v.z, v.w);
        uint2 u;
        u.x = *reinterpret_cast<unsigned*>(&h0);
        u.y = *reinterpret_cast<unsigned*>(&h1);
        ((uint2*)dst)[i] = u;
    }
}

// ---------------------------------------------------------------------------
// fp16-input NT GEMM: C[M,N] = A[M,Kd] * B[N,Kd]^T + bias[N], optional sigmoid.
// A,B pre-converted to fp16 (K-major). cp.async 2-stage double buffer, BK=32,
// 128x128 tile, 256 thr (8 warps 2x4), warp tile 64x32 via m16n8k16, fp32 acc.
// Row pitch KP=40 halves (80B = 5x16B) -> aligned cp.async + conflict-free
// ldmatrix. 2 CTAs/SM -> grid runs in ~one wave.
// ---------------------------------------------------------------------------
#define KP 40
__global__ void __launch_bounds__(256, 2) gemm_h_nt(
    const __half* __restrict__ A, const __half* __restrict__ B,
    const float* __restrict__ bias, float* __restrict__ C,
    int M, int N, int Kd, int act)
{
    __shared__ __half As[2][128 * KP];
    __shared__ __half Bs[2][128 * KP];

    const int tid = threadIdx.x;
    const int lane = tid & 31;
    const int wid = tid >> 5;
    const int warpM = wid >> 2;     // 0..1
    const int warpN = wid & 3;      // 0..3
    const int bm = blockIdx.y * 128;
    const int bn = blockIdx.x * 128;

    float acc[4][4][4];
#pragma unroll
    for (int a = 0; a < 4; a++)
#pragma unroll
        for (int b = 0; b < 4; b++)
#pragma unroll
            for (int c = 0; c < 4; c++) acc[a][b][c] = 0.f;

    const int iters = Kd / 32;

    // stage loader: 128 rows x 32 halves (4x 16B chunks/row), A and B
#define LOAD_TILE(buf, k0)                                                     \
    {                                                                          \
        _Pragma("unroll")                                                      \
        for (int p = 0; p < 2; p++) {                                          \
            const int c = tid + p * 256;                                       \
            const int row = c >> 2;                                            \
            const int col = (c & 3) * 8;                                       \
            cp_async16(&As[buf][row * KP + col],                               \
                       A + (size_t)(bm + row) * Kd + (k0) + col);              \
            cp_async16(&Bs[buf][row * KP + col],                               \
                       B + (size_t)(bn + row) * Kd + (k0) + col);              \
        }                                                                      \
    }

    LOAD_TILE(0, 0);
    CP_COMMIT();

    for (int it = 0; it < iters; ++it) {
        if (it + 1 < iters) {
            LOAD_TILE((it + 1) & 1, (it + 1) * 32);
            CP_COMMIT();
            CP_WAIT(1);
        } else {
            CP_WAIT(0);
        }
        __syncthreads();

        const __half* Ab = As[it & 1];
        const __half* Bb = Bs[it & 1];
#pragma unroll
        for (int ks = 0; ks < 2; ks++) {
            const int k0 = ks * 16;
            uint32_t afr[4][4];
            uint32_t bfr[4][2];
#pragma unroll
            for (int fm = 0; fm < 4; fm++) {
                const __half* p = &Ab[(warpM * 64 + fm * 16 + (lane & 7) +
                                       ((lane >> 3) & 1) * 8) * KP +
                                      k0 + (lane >> 4) * 8];
                ldm_x4(afr[fm], p);
            }
#pragma unroll
            for (int fp = 0; fp < 2; fp++) {
                uint32_t r[4];
                const __half* p = &Bb[(warpN * 32 + fp * 16 + (lane & 7) +
                                       (lane >> 4) * 8) * KP +
                                      k0 + ((lane >> 3) & 1) * 8];
                ldm_x4(r, p);
                bfr[2 * fp][0] = r[0];     bfr[2 * fp][1] = r[1];
                bfr[2 * fp + 1][0] = r[2]; bfr[2 * fp + 1][1] = r[3];
            }
#pragma unroll
            for (int fm = 0; fm < 4; fm++)
#pragma unroll
                for (int fn = 0; fn < 4; fn++)
                    mma16816(acc[fm][fn], afr[fm], bfr[fn]);
        }
        __syncthreads();
    }
#undef LOAD_TILE

    // epilogue: bias + optional sigmoid
#pragma unroll
    for (int fm = 0; fm < 4; fm++)
#pragma unroll
        for (int fn = 0; fn < 4; fn++)
#pragma unroll
            for (int h = 0; h < 2; h++) {
                const int row = bm + warpM * 64 + fm * 16 + (lane >> 2) + h * 8;
                const int col = bn + warpN * 32 + fn * 8 + (lane & 3) * 2;
                float c0 = acc[fm][fn][2 * h]     + __ldg(&bias[col]);
                float c1 = acc[fm][fn][2 * h + 1] + __ldg(&bias[col + 1]);
                if (act) {
                    c0 = 1.f / (1.f + expf(-c0));
                    c1 = 1.f / (1.f + expf(-c1));
                }
                *(float2*)(C + (size_t)row * N + col) = make_float2(c0, c1);
            }
}

// ---------------------------------------------------------------------------
// Gated linear-recurrence scan, K-packed fp32x2 state, 2 CTAs/SM.
//   state[k][v] = state[k][v]*g_t[k] + k_t[k]*v_t[v];  out_t = q_t . state
// 256 CTAs x 256 thr. CTA owns 4 V-cols (vbase=4*bid); thread owns K rows
// [4*tid,4*tid+4) as 2 packed K-pairs x 4 cols -> 8 u64 state regs.
// q/k/g packed operands are free reinterprets of the float4 load; only v
// needs lane duplication. Reduction: 4 values -> 5 shuffles. One barrier per
// 2 steps (4-deep parity smem). 4 warps/SMSP hides shfl + L2 latency.
// ---------------------------------------------------------------------------
__global__ void __launch_bounds__(256, 2) scan_kernel(
    const float* __restrict__ q, const float* __restrict__ kv_k,
    const float* __restrict__ gv, const float* __restrict__ vv,
    float* __restrict__ opre, float* __restrict__ state_out)
{
    __shared__ float sred[4][8][4];   // [parity4][warp][vcol]

    const int tid  = threadIdx.x;
    const int wid  = tid >> 5;
    const int lane = tid & 31;
    const int vbase = blockIdx.x * 4;
    const int kbase = tid * 4;

    unsigned long long s2[2][4];
#pragma unroll
    for (int ip = 0; ip < 2; ip++)
#pragma unroll
        for (int j = 0; j < 4; j++) s2[ip][j] = pk2(0.f, 0.f);

    // prefetch step 0 (q/k/g as packed pairs via 16B loads)
    ulonglong2 pq = *(const ulonglong2*)(q    + kbase);
    ulonglong2 pk = *(const ulonglong2*)(kv_k + kbase);
    ulonglong2 pg = *(const ulonglong2*)(gv   + kbase);
    float4     pv = *(const float4*)(vv + vbase);

    for (int t = 0; t < T_DIM; t += 2) {
#pragma unroll
        for (int sub = 0; sub < 2; sub++) {
            const int tt = t + sub;
            const ulonglong2 cq = pq, ck = pk, cg = pg;
            const float4 cv = pv;

            if (tt + 1 < T_DIM) {
                const size_t off = (size_t)(tt + 1) * K_DIM + kbase;
                pq = *(const ulonglong2*)(q    + off);
                pk = *(const ulonglong2*)(kv_k + off);
                pg = *(const ulonglong2*)(gv   + off);
                pv = *(const float4*)(vv + (size_t)(tt + 1) * V_DIM + vbase);
            }

            unsigned long long vd[4];
            vd[0] = pk2(cv.x, cv.x);
            vd[1] = pk2(cv.y, cv.y);
            vd[2] = pk2(cv.z, cv.z);
            vd[3] = pk2(cv.w, cv.w);

            unsigned long long po2[4];
#pragma unroll
            for (int j = 0; j < 4; j++) po2[j] = pk2(0.f, 0.f);

#pragma unroll
            for (int ip = 0; ip < 2; ip++) {
                const unsigned long long q2 = ip ? cq.y : cq.x;
                const unsigned long long k2 = ip ? ck.y : ck.x;
                const unsigned long long g2 = ip ? cg.y : cg.x;
#pragma unroll
                for (int j = 0; j < 4; j++) {
                    s2[ip][j] = fma2(s2[ip][j], g2, mul2(k2, vd[j]));
                    po2[j]    = fma2(q2, s2[ip][j], po2[j]);
                }
            }

            float po[4];
#pragma unroll
            for (int j = 0; j < 4; j++) {
                float lo, hi;
                upk2(po2[j], lo, hi);
                po[j] = lo + hi;
            }

            // value-halving butterfly: xor2, xor1 -> lane holds col (lane&3)
            // partial over its 4-lane group; xor4/8/16 finish the warp sum.
            const bool b1 = (lane & 2) != 0;
            float s0 = b1 ? po[0] : po[2];
            float s1 = b1 ? po[1] : po[3];
            float r0 = __shfl_xor_sync(0xffffffffu, s0, 2);
            float r1 = __shfl_xor_sync(0xffffffffu, s1, 2);
            float u0 = (b1 ? po[2] : po[0]) + r0;
            float u1 = (b1 ? po[3] : po[1]) + r1;

            const bool b0 = (lane & 1) != 0;
            float s = b0 ? u0 : u1;
            float rr = __shfl_xor_sync(0xffffffffu, s, 1);
            float r = (b0 ? u1 : u0) + rr;

            r += __shfl_xor_sync(0xffffffffu, r, 4);
            r += __shfl_xor_sync(0xffffffffu, r, 8);
            r += __shfl_xor_sync(0xffffffffu, r, 16);

            if (lane < 4) sred[tt & 3][wid][lane] = r;
        }

        __syncthreads();
        if (tid < 8) {
            const int tt = t + (tid >> 2);
            const int j = tid & 3;
            float x = 0.f;
#pragma unroll
            for (int w = 0; w < 8; w++) x += sred[tt & 3][w][j];
            opre[(size_t)tt * V_DIM + vbase + j] = x;
        }
        // depth-4 buffers: slots for steps t,t+1 are rewritten only two
        // barriers later -> reader has always finished.
    }

    // final state -> global (K,V) row-major
#pragma unroll
    for (int ip = 0; ip < 2; ip++) {
        float lo[4], hi[4];
#pragma unroll
        for (int j = 0; j < 4; j++) upk2(s2[ip][j], lo[j], hi[j]);
        *(float4*)(state_out + (size_t)(kbase + 2 * ip) * V_DIM + vbase) =
            make_float4(lo[0], lo[1], lo[2], lo[3]);
        *(float4*)(state_out + (size_t)(kbase + 2 * ip + 1) * V_DIM + vbase) =
            make_float4(hi[0], hi[1], hi[2], hi[3]);
    }
}

// ---------------------------------------------------------------------------
extern "C" void kernel_launch(void* const* d_in, const int* in_sizes, int n_in,
                              void* d_out, int out_size)
{
    const float* X  = (const float*)d_in[0];
    const float* Wq = (const float*)d_in[1];
    const float* bq = (const float*)d_in[2];
    const float* Wk = (const float*)d_in[3];
    const float* bk = (const float*)d_in[4];
    const float* Wv = (const float*)d_in[5];
    const float* bv = (const float*)d_in[6];
    const float* Wg = (const float*)d_in[7];
    const float* bg = (const float*)d_in[8];
    const float* Wo = (const float*)d_in[9];
    const float* bo = (const float*)d_in[10];
    float* out = (float*)d_out;

    float* scratch = 0;
    cudaGetSymbolAddress((void**)&scratch, g_scratch);
    float* qb    = scratch;
    float* kb    = qb   + (size_t)T_DIM * K_DIM;
    float* gb    = kb   + (size_t)T_DIM * K_DIM;
    float* vb    = gb   + (size_t)T_DIM * K_DIM;
    float* opre  = vb   + (size_t)T_DIM * V_DIM;
    float* sdump = opre + (size_t)T_DIM * V_DIM;

    __half* hscr = 0;
    cudaGetSymbolAddress((void**)&hscr, g_scratch_h);
    __half* Xh    = hscr;
    __half* Wqh   = Xh   + (size_t)T_DIM * H_DIM;
    __half* Wkh   = Wqh  + (size_t)K_DIM * H_DIM;
    __half* Wgh   = Wkh  + (size_t)K_DIM * H_DIM;
    __half* Wvh   = Wgh  + (size_t)K_DIM * H_DIM;
    __half* Woh   = Wvh  + (size_t)K_DIM * H_DIM;
    __half* opreh = Woh  + (size_t)O_DIM * V_DIM;

    const size_t out_main = (size_t)T_DIM * O_DIM;
    const size_t out_full = out_main + (size_t)K_DIM * V_DIM;
    float* state_out = ((size_t)out_size >= out_full) ? (out + out_main) : sdump;

    dim3 blk(256);

    // one-time fp32->fp16 conversions
    f2h_kernel<<<2048, 256>>>(X,  Xh,  (int)((size_t)T_DIM * H_DIM / 4));
    f2h_kernel<<<1024, 256>>>(Wq, Wqh, (int)((size_t)K_DIM * H_DIM / 4));
    f2h_kernel<<<1024, 256>>>(Wk, Wkh, (int)((size_t)K_DIM * H_DIM / 4));
    f2h_kernel<<<1024, 256>>>(Wg, Wgh, (int)((size_t)K_DIM * H_DIM / 4));
    f2h_kernel<<<1024, 256>>>(Wv, Wvh, (int)((size_t)K_DIM * H_DIM / 4));
    f2h_kernel<<<1024, 256>>>(Wo, Woh, (int)((size_t)O_DIM * V_DIM / 4));

    // projections: q (linear), k (sigmoid), g (sigmoid), v (linear)
    gemm_h_nt<<<dim3(K_DIM / 128, T_DIM / 128), blk>>>(Xh, Wqh, bq, qb, T_DIM, K_DIM, H_DIM, 0);
    gemm_h_nt<<<dim3(K_DIM / 128, T_DIM / 128), blk>>>(Xh, Wkh, bk, kb, T_DIM, K_DIM, H_DIM, 1);
    gemm_h_nt<<<dim3(K_DIM / 128, T_DIM / 128), blk>>>(Xh, Wgh, bg, gb, T_DIM, K_DIM, H_DIM, 1);
    gemm_h_nt<<<dim3(V_DIM / 128, T_DIM / 128), blk>>>(Xh, Wvh, bv, vb, T_DIM, V_DIM, H_DIM, 0);

    // sequential gated scan (2 CTAs/SM)
    scan_kernel<<<256, blk>>>(qb, kb, gb, vb, opre, state_out);

    // opre -> fp16, then output projection
    f2h_kernel<<<1024, 256>>>(opre, opreh, (int)((size_t)T_DIM * V_DIM / 4));
    gemm_h_nt<<<dim3(O_DIM / 128, T_DIM / 128), blk>>>(opreh, Woh, bo, out, T_DIM, O_DIM, V_DIM, 0);
}

// round 8
// speedup vs baseline: 1.8280x; 1.8280x over previous
#include <cuda_runtime.h>
#include <cuda_fp16.h>
#include <math.h>
#include <stddef.h>
#include <stdint.h>

typedef unsigned long long ull;

#define T_DIM 4096
#define H_DIM 2048
#define K_DIM 1024
#define V_DIM 1024
#define O_DIM 2048
#define CHUNK 32
#define NCHUNK 128

// fp32 scratch: q | k | g | v | qa | kia | kh | opre | a15 | sdump
__device__ __align__(16) float g_scratch[(size_t)6 * T_DIM * K_DIM +
                                         (size_t)2 * T_DIM * V_DIM +
                                         (size_t)NCHUNK * K_DIM +
                                         (size_t)K_DIM * V_DIM];
// fp16 scratch: Xh | Wqh | Wkh | Wgh | Wvh | Woh | opreh | qah | Ssnap
__device__ __align__(16) __half g_scratch_h[(size_t)T_DIM * H_DIM +
                                            (size_t)4 * K_DIM * H_DIM +
                                            (size_t)O_DIM * V_DIM +
                                            (size_t)T_DIM * V_DIM +
                                            (size_t)T_DIM * K_DIM +
                                            (size_t)NCHUNK * K_DIM * V_DIM];

// ---------------- packed f32x2 helpers ----------------
__device__ __forceinline__ ull pk2(float lo, float hi) {
    ull r; asm("mov.b64 %0, {%1, %2};" : "=l"(r) : "f"(lo), "f"(hi)); return r;
}
__device__ __forceinline__ void upk2(ull v, float& lo, float& hi) {
    asm("mov.b64 {%0, %1}, %2;" : "=f"(lo), "=f"(hi) : "l"(v));
}
__device__ __forceinline__ ull fma2(ull a, ull b, ull c) {
    ull d; asm("fma.rn.f32x2 %0, %1, %2, %3;" : "=l"(d) : "l"(a), "l"(b), "l"(c)); return d;
}
__device__ __forceinline__ ull mul2(ull a, ull b) {
    ull d; asm("mul.rn.f32x2 %0, %1, %2;" : "=l"(d) : "l"(a), "l"(b)); return d;
}

// ---------------- tensor-core + cp.async helpers ----------------
__device__ __forceinline__ void ldm_x4(uint32_t* r, const __half* p) {
    uint32_t addr = (uint32_t)__cvta_generic_to_shared(p);
    asm volatile("ldmatrix.sync.aligned.m8n8.x4.shared.b16 {%0,%1,%2,%3}, [%4];"
                 : "=r"(r[0]), "=r"(r[1]), "=r"(r[2]), "=r"(r[3]) : "r"(addr));
}
__device__ __forceinline__ void mma16816(float* d, const uint32_t* a, const uint32_t* b) {
    asm volatile(
        "mma.sync.aligned.m16n8k16.row.col.f32.f16.f16.f32 "
        "{%0,%1,%2,%3}, {%4,%5,%6,%7}, {%8,%9}, {%0,%1,%2,%3};"
        : "+f"(d[0]), "+f"(d[1]), "+f"(d[2]), "+f"(d[3])
        : "r"(a[0]), "r"(a[1]), "r"(a[2]), "r"(a[3]), "r"(b[0]), "r"(b[1]));
}
__device__ __forceinline__ void cp_async16(__half* smem_dst, const __half* gsrc) {
    uint32_t d = (uint32_t)__cvta_generic_to_shared(smem_dst);
    asm volatile("cp.async.cg.shared.global [%0], [%1], 16;" :: "r"(d), "l"(gsrc));
}
#define CP_COMMIT() asm volatile("cp.async.commit_group;")
#define CP_WAIT(n)  asm volatile("cp.async.wait_group %0;" :: "n"(n))

// ---------------- fp32 -> fp16 convert ----------------
__global__ void f2h_kernel(const float* __restrict__ src, __half* __restrict__ dst, int n4)
{
    int i = blockIdx.x * blockDim.x + threadIdx.x;
    const int stride = gridDim.x * blockDim.x;
    for (; i < n4; i += stride) {
        float4 v = ((const float4*)src)[i];
        __half2 h0 = __floats2half2_rn(v.x, v.y);
        __half2 h1 = __floats2half2_rn(v.z, v.w);
        uint2 u;
        u.x = *reinterpret_cast<unsigned*>(&h0);
        u.y = *reinterpret_cast<unsigned*>(&h1);
        ((uint2*)dst)[i] = u;
    }
}

// ---------------- fp16 NT GEMM (proven R4 kernel, unchanged) ----------------
#define KP 40
__global__ void __launch_bounds__(256, 2) gemm_h_nt(
    const __half* __restrict__ A, const __half* __restrict__ B,
    const float* __restrict__ bias, float* __restrict__ C,
    int M, int N, int Kd, int act)
{
    __shared__ __half As[2][128 * KP];
    __shared__ __half Bs[2][128 * KP];

    const int tid = threadIdx.x;
    const int lane = tid & 31;
    const int wid = tid >> 5;
    const int warpM = wid >> 2;
    const int warpN = wid & 3;
    const int bm = blockIdx.y * 128;
    const int bn = blockIdx.x * 128;

    float acc[4][4][4];
#pragma unroll
    for (int a = 0; a < 4; a++)
#pragma unroll
        for (int b = 0; b < 4; b++)
#pragma unroll
            for (int c = 0; c < 4; c++) acc[a][b][c] = 0.f;

    const int iters = Kd / 32;

#define LOAD_TILE(buf, k0)                                                     \
    {                                                                          \
        _Pragma("unroll")                                                      \
        for (int p = 0; p < 2; p++) {                                          \
            const int c = tid + p * 256;                                       \
            const int row = c >> 2;                                            \
            const int col = (c & 3) * 8;                                       \
            cp_async16(&As[buf][row * KP + col],                               \
                       A + (size_t)(bm + row) * Kd + (k0) + col);              \
            cp_async16(&Bs[buf][row * KP + col],                               \
                       B + (size_t)(bn + row) * Kd + (k0) + col);              \
        }                                                                      \
    }

    LOAD_TILE(0, 0);
    CP_COMMIT();

    for (int it = 0; it < iters; ++it) {
        if (it + 1 < iters) {
            LOAD_TILE((it + 1) & 1, (it + 1) * 32);
            CP_COMMIT();
            CP_WAIT(1);
        } else {
            CP_WAIT(0);
        }
        __syncthreads();

        const __half* Ab = As[it & 1];
        const __half* Bb = Bs[it & 1];
#pragma unroll
        for (int ks = 0; ks < 2; ks++) {
            const int k0 = ks * 16;
            uint32_t afr[4][4];
            uint32_t bfr[4][2];
#pragma unroll
            for (int fm = 0; fm < 4; fm++) {
                const __half* p = &Ab[(warpM * 64 + fm * 16 + (lane & 7) +
                                       ((lane >> 3) & 1) * 8) * KP +
                                      k0 + (lane >> 4) * 8];
                ldm_x4(afr[fm], p);
            }
#pragma unroll
            for (int fp = 0; fp < 2; fp++) {
                uint32_t r[4];
                const __half* p = &Bb[(warpN * 32 + fp * 16 + (lane & 7) +
                                       (lane >> 4) * 8) * KP +
                                      k0 + ((lane >> 3) & 1) * 8];
                ldm_x4(r, p);
                bfr[2 * fp][0] = r[0];     bfr[2 * fp][1] = r[1];
                bfr[2 * fp + 1][0] = r[2]; bfr[2 * fp + 1][1] = r[3];
            }
#pragma unroll
            for (int fm = 0; fm < 4; fm++)
#pragma unroll
                for (int fn = 0; fn < 4; fn++)
                    mma16816(acc[fm][fn], afr[fm], bfr[fn]);
        }
        __syncthreads();
    }
#undef LOAD_TILE

#pragma unroll
    for (int fm = 0; fm < 4; fm++)
#pragma unroll
        for (int fn = 0; fn < 4; fn++)
#pragma unroll
            for (int h = 0; h < 2; h++) {
                const int row = bm + warpM * 64 + fm * 16 + (lane >> 2) + h * 8;
                const int col = bn + warpN * 32 + fn * 8 + (lane & 3) * 2;
                float c0 = acc[fm][fn][2 * h]     + __ldg(&bias[col]);
                float c1 = acc[fm][fn][2 * h + 1] + __ldg(&bias[col + 1]);
                if (act) {
                    c0 = 1.f / (1.f + expf(-c0));
                    c1 = 1.f / (1.f + expf(-c1));
                }
                *(float2*)(C + (size_t)row * N + col) = make_float2(c0, c1);
            }
}

// ---------------- prep: per-chunk cumulative gates ----------------
// A_u[k] = prod_{r<=u} g_r[k]  (within chunk). Emits:
//   qa  = q * A_u        (fp32)     qah = fp16(qa)
//   kia = k / A_u        (fp32, IEEE div; A >= ~1e-24 -> safe)
//   kh  = k * A_31/A_u   (fp32)     a15 = A_31 per chunk
__global__ void __launch_bounds__(256) prep_kernel(
    const float* __restrict__ q, const float* __restrict__ kk,
    const float* __restrict__ g, float* __restrict__ qa,
    __half* __restrict__ qah, float* __restrict__ kia,
    float* __restrict__ kh, float* __restrict__ a15)
{
    const int cid = blockIdx.x;
    const int kc = threadIdx.x * 4;
    const size_t t0 = (size_t)cid * CHUNK;
    float4 A = make_float4(1.f, 1.f, 1.f, 1.f);
#pragma unroll 4
    for (int u = 0; u < CHUNK; u++) {
        const size_t off = (t0 + u) * K_DIM + kc;
        float4 gv = *(const float4*)(g + off);
        A.x *= gv.x; A.y *= gv.y; A.z *= gv.z; A.w *= gv.w;
        float4 qv = *(const float4*)(q + off);
        float4 qa4 = make_float4(qv.x * A.x, qv.y * A.y, qv.z * A.z, qv.w * A.w);
        *(float4*)(qa + off) = qa4;
        __half2 h0 = __floats2half2_rn(qa4.x, qa4.y);
        __half2 h1 = __floats2half2_rn(qa4.z, qa4.w);
        uint2 uu; uu.x = *(unsigned*)&h0; uu.y = *(unsigned*)&h1;
        *(uint2*)(qah + off) = uu;
        float4 kv = *(const float4*)(kk + off);
        float4 ki = make_float4(__fdiv_rn(kv.x, A.x), __fdiv_rn(kv.y, A.y),
                                __fdiv_rn(kv.z, A.z), __fdiv_rn(kv.w, A.w));
        *(float4*)(kia + off) = ki;
    }
    *(float4*)(a15 + (size_t)cid * K_DIM + kc) = A;
#pragma unroll 4
    for (int u = 0; u < CHUNK; u++) {
        const size_t off = (t0 + u) * K_DIM + kc;
        float4 ki = *(const float4*)(kia + off);
        *(float4*)(kh + off) =
            make_float4(ki.x * A.x, ki.y * A.y, ki.z * A.z, ki.w * A.w);
    }
}

// ---------------- intra-chunk: P = QA @ KIA^T (masked), out = P @ V ----------
// One CTA per chunk. Phase 1: 8x8 entry block x 16-way k-split per thread,
// smem-staged k-tiles, atomic smem reduction. Phase 2: masked P @ V.
// PAD = 4 floats so row stride (TS+4=132) keeps float4 smem stores 16B-aligned
// (R7 bug: +1 pad trapped with 'misaligned address').
#define TS 128
__global__ void __launch_bounds__(256) intra_kernel(
    const float* __restrict__ qa, const float* __restrict__ kia,
    const float* __restrict__ vv, float* __restrict__ opre)
{
    __shared__ float qs[CHUNK][TS + 4];
    __shared__ float ks_[CHUNK][TS + 4];
    __shared__ float Ps[CHUNK][CHUNK + 1];
    const int tid = threadIdx.x;
    const int cid = blockIdx.x;
    const size_t t0 = (size_t)cid * CHUNK;

    for (int i = tid; i < CHUNK * (CHUNK + 1); i += 256)
        ((float*)Ps)[i] = 0.f;

    const int u0 = ((tid >> 2) & 3) * 8;
    const int s0 = (tid & 3) * 8;
    const int ksl = tid >> 4;   // 0..15
    float acc[8][8];
#pragma unroll
    for (int i = 0; i < 8; i++)
#pragma unroll
        for (int j = 0; j < 8; j++) acc[i][j] = 0.f;

    for (int kt = 0; kt < K_DIM; kt += TS) {
        __syncthreads();
#pragma unroll
        for (int p = 0; p < 4; p++) {
            int idx = tid + p * 256;          // 0..1023
            int rr = idx >> 5;                // 0..31
            int cc = (idx & 31) * 4;          // 0..124
            *(float4*)&qs[rr][cc]  = *(const float4*)(qa  + (t0 + rr) * K_DIM + kt + cc);
            *(float4*)&ks_[rr][cc] = *(const float4*)(kia + (t0 + rr) * K_DIM + kt + cc);
        }
        __syncthreads();
        const int kb = ksl * 8;
#pragma unroll
        for (int km = 0; km < 8; km++) {
            const int kx = kb + km;
            float qv[8], kv[8];
#pragma unroll
            for (int i = 0; i < 8; i++) qv[i] = qs[u0 + i][kx];
#pragma unroll
            for (int j = 0; j < 8; j++) kv[j] = ks_[s0 + j][kx];
#pragma unroll
            for (int i = 0; i < 8; i++)
#pragma unroll
                for (int j = 0; j < 8; j++)
                    acc[i][j] = fmaf(qv[i], kv[j], acc[i][j]);
        }
    }
    __syncthreads();
#pragma unroll
    for (int i = 0; i < 8; i++)
#pragma unroll
        for (int j = 0; j < 8; j++)
            atomicAdd(&Ps[u0 + i][s0 + j], acc[i][j]);
    __syncthreads();

    // phase 2: out[u][v] = sum_{s<=u} P[u][s] * v_s[v]; thread owns 4 v-cols
    const int vc = tid * 4;
#pragma unroll
    for (int pass = 0; pass < 4; pass++) {
        float o[8][4];
#pragma unroll
        for (int i = 0; i < 8; i++) { o[i][0] = o[i][1] = o[i][2] = o[i][3] = 0.f; }
        for (int s = 0; s < CHUNK; s++) {
            float4 v4 = *(const float4*)(vv + (t0 + s) * V_DIM + vc);
#pragma unroll
            for (int i = 0; i < 8; i++) {
                const int u = pass * 8 + i;
                float p = (s <= u) ? Ps[u][s] : 0.f;
                o[i][0] = fmaf(p, v4.x, o[i][0]);
                o[i][1] = fmaf(p, v4.y, o[i][1]);
                o[i][2] = fmaf(p, v4.z, o[i][2]);
                o[i][3] = fmaf(p, v4.w, o[i][3]);
            }
        }
#pragma unroll
        for (int i = 0; i < 8; i++) {
            const int u = pass * 8 + i;
            *(float4*)(opre + (t0 + u) * V_DIM + vc) =
                make_float4(o[i][0], o[i][1], o[i][2], o[i][3]);
        }
    }
}

// ---------------- serial: 128 chunk iterations over 2D-partitioned state ----
// 128 CTAs = 4 K-groups x 32 V-slices; thread owns 4 K-rows x 8 V-cols.
// Per chunk: fp16 snapshot (pre-update, v-major = NT B layout for inter GEMM),
// decay by a15, 32 rank-1 f32x2 updates. No cross-thread communication.
__global__ void __launch_bounds__(256, 1) serial_kernel(
    const float* __restrict__ kh, const float* __restrict__ a15,
    const float* __restrict__ vv, __half* __restrict__ snap,
    float* __restrict__ state_out)
{
    const int tid = threadIdx.x;
    const int kg = blockIdx.x & 3;
    const int vs = blockIdx.x >> 2;
    const int vt = tid >> 6;          // 0..3
    const int kt = tid & 63;          // 0..63
    const int kbase = kg * 256 + kt * 4;
    const int vbase = vs * 32 + vt * 8;

    ull s2[4][4];                     // [k-row][v-pair]
#pragma unroll
    for (int i = 0; i < 4; i++)
#pragma unroll
        for (int jp = 0; jp < 4; jp++) s2[i][jp] = pk2(0.f, 0.f);

    for (int cid = 0; cid < NCHUNK; cid++) {
        // snapshot pre-update state -> snap[cid][v][k] fp16 (coalesced 8B/thread)
#pragma unroll
        for (int jp = 0; jp < 4; jp++) {
            float a0, a1, b0, b1, c0, c1, d0, d1;
            upk2(s2[0][jp], a0, a1);
            upk2(s2[1][jp], b0, b1);
            upk2(s2[2][jp], c0, c1);
            upk2(s2[3][jp], d0, d1);
            __half2 h00 = __floats2half2_rn(a0, b0);
            __half2 h01 = __floats2half2_rn(c0, d0);
            uint2 w0; w0.x = *(unsigned*)&h00; w0.y = *(unsigned*)&h01;
            *(uint2*)(snap + ((size_t)cid * V_DIM + vbase + 2 * jp) * K_DIM + kbase) = w0;
            __half2 h10 = __floats2half2_rn(a1, b1);
            __half2 h11 = __floats2half2_rn(c1, d1);
            uint2 w1; w1.x = *(unsigned*)&h10; w1.y = *(unsigned*)&h11;
            *(uint2*)(snap + ((size_t)cid * V_DIM + vbase + 2 * jp + 1) * K_DIM + kbase) = w1;
        }
        // decay once per chunk
        float4 af = *(const float4*)(a15 + (size_t)cid * K_DIM + kbase);
        ull ad0 = pk2(af.x, af.x), ad1 = pk2(af.y, af.y);
        ull ad2 = pk2(af.z, af.z), ad3 = pk2(af.w, af.w);
#pragma unroll
        for (int jp = 0; jp < 4; jp++) {
            s2[0][jp] = mul2(s2[0][jp], ad0);
            s2[1][jp] = mul2(s2[1][jp], ad1);
            s2[2][jp] = mul2(s2[2][jp], ad2);
            s2[3][jp] = mul2(s2[3][jp], ad3);
        }
        // 32 rank-1 updates
        const size_t tb = (size_t)cid * CHUNK;
#pragma unroll 4
        for (int st = 0; st < CHUNK; st++) {
            const size_t t = tb + st;
            float4 k4 = *(const float4*)(kh + t * K_DIM + kbase);
            float4 v0 = *(const float4*)(vv + t * V_DIM + vbase);
            float4 v1 = *(const float4*)(vv + t * V_DIM + vbase + 4);
            ull vp[4] = {pk2(v0.x, v0.y), pk2(v0.z, v0.w),
                         pk2(v1.x, v1.y), pk2(v1.z, v1.w)};
            ull kd[4] = {pk2(k4.x, k4.x), pk2(k4.y, k4.y),
                         pk2(k4.z, k4.z), pk2(k4.w, k4.w)};
#pragma unroll
            for (int i = 0; i < 4; i++)
#pragma unroll
                for (int jp = 0; jp < 4; jp++)
                    s2[i][jp] = fma2(kd[i], vp[jp], s2[i][jp]);
        }
    }

    // final state -> (K,V) row-major
#pragma unroll
    for (int i = 0; i < 4; i++) {
        float f[8];
#pragma unroll
        for (int jp = 0; jp < 4; jp++) upk2(s2[i][jp], f[2 * jp], f[2 * jp + 1]);
        *(float4*)(state_out + (size_t)(kbase + i) * V_DIM + vbase) =
            make_float4(f[0], f[1], f[2], f[3]);
        *(float4*)(state_out + (size_t)(kbase + i) * V_DIM + vbase + 4) =
            make_float4(f[4], f[5], f[6], f[7]);
    }
}

// ---------------- inter: opre += qa_chunk @ snapshot^T (tensor cores) -------
// grid (8 vtiles, 127 chunks); CTA: M=32, N=128, K=1024, fp16 mma, fp32 acc.
__global__ void __launch_bounds__(256) inter_kernel(
    const __half* __restrict__ qah, const __half* __restrict__ snap,
    float* __restrict__ opre)
{
    __shared__ __half As[2][32 * KP];
    __shared__ __half Bs[2][128 * KP];
    const int tid = threadIdx.x;
    const int lane = tid & 31;
    const int wid = tid >> 5;
    const int warpM = wid >> 2;     // 0..1 -> 16 rows each
    const int warpN = wid & 3;      // 0..3 -> 32 cols each
    const int vt = blockIdx.x;
    const int cid = blockIdx.y + 1;   // chunk 0 has zero snapshot: skipped

    const __half* A = qah + (size_t)cid * CHUNK * K_DIM;
    const __half* B = snap + ((size_t)cid * V_DIM + vt * 128) * K_DIM;

    float acc[4][4];
#pragma unroll
    for (int a = 0; a < 4; a++)
#pragma unroll
        for (int c = 0; c < 4; c++) acc[a][c] = 0.f;

#define LOAD_TILE_I(buf, k0)                                                   \
    {                                                                          \
        if (tid < 128) {                                                       \
            const int row = tid >> 2;                                          \
            const int col = (tid & 3) * 8;                                     \
            cp_async16(&As[buf][row * KP + col],                               \
                       A + (size_t)row * K_DIM + (k0) + col);                  \
        }                                                                      \
        _Pragma("unroll")                                                      \
        for (int p = 0; p < 2; p++) {                                          \
            const int c = tid + p * 256;                                       \
            const int row = c >> 2;                                            \
            const int col = (c & 3) * 8;                                       \
            cp_async16(&Bs[buf][row * KP + col],                               \
                       B + (size_t)row * K_DIM + (k0) + col);                  \
        }                                                                      \
    }

    LOAD_TILE_I(0, 0);
    CP_COMMIT();
    const int iters = K_DIM / 32;
    for (int it = 0; it < iters; ++it) {
        if (it + 1 < iters) {
            LOAD_TILE_I((it + 1) & 1, (it + 1) * 32);
            CP_COMMIT();
            CP_WAIT(1);
        } else {
            CP_WAIT(0);
        }
        __syncthreads();
        const __half* Ab = As[it & 1];
        const __half* Bb = Bs[it & 1];
#pragma unroll
        for (int ks = 0; ks < 2; ks++) {
            const int k0 = ks * 16;
            uint32_t afr[4];
            uint32_t bfr[4][2];
            {
                const __half* p = &Ab[(warpM * 16 + (lane & 7) +
                                       ((lane >> 3) & 1) * 8) * KP +
                                      k0 + (lane >> 4) * 8];
                ldm_x4(afr, p);
            }
#pragma unroll
            for (int fp = 0; fp < 2; fp++) {
                uint32_t r[4];
                const __half* p = &Bb[(warpN * 32 + fp * 16 + (lane & 7) +
                                       (lane >> 4) * 8) * KP +
                                      k0 + ((lane >> 3) & 1) * 8];
                ldm_x4(r, p);
                bfr[2 * fp][0] = r[0];     bfr[2 * fp][1] = r[1];
                bfr[2 * fp + 1][0] = r[2]; bfr[2 * fp + 1][1] = r[3];
            }
#pragma unroll
            for (int fn = 0; fn < 4; fn++) mma16816(acc[fn], afr, bfr[fn]);
        }
        __syncthreads();
    }
#undef LOAD_TILE_I

#pragma unroll
    for (int fn = 0; fn < 4; fn++)
#pragma unroll
        for (int h = 0; h < 2; h++) {
            const int row = cid * CHUNK + warpM * 16 + (lane >> 2) + h * 8;
            const int col = vt * 128 + warpN * 32 + fn * 8 + (lane & 3) * 2;
            float2 o = *(float2*)(opre + (size_t)row * V_DIM + col);
            o.x += acc[fn][2 * h];
            o.y += acc[fn][2 * h + 1];
            *(float2*)(opre + (size_t)row * V_DIM + col) = o;
        }
}

// ---------------------------------------------------------------------------
extern "C" void kernel_launch(void* const* d_in, const int* in_sizes, int n_in,
                              void* d_out, int out_size)
{
    const float* X  = (const float*)d_in[0];
    const float* Wq = (const float*)d_in[1];
    const float* bq = (const float*)d_in[2];
    const float* Wk = (const float*)d_in[3];
    const float* bk = (const float*)d_in[4];
    const float* Wv = (const float*)d_in[5];
    const float* bv = (const float*)d_in[6];
    const float* Wg = (const float*)d_in[7];
    const float* bg = (const float*)d_in[8];
    const float* Wo = (const float*)d_in[9];
    const float* bo = (const float*)d_in[10];
    float* out = (float*)d_out;

    float* scratch = 0;
    cudaGetSymbolAddress((void**)&scratch, g_scratch);
    float* qb    = scratch;
    float* kb    = qb   + (size_t)T_DIM * K_DIM;
    float* gb    = kb   + (size_t)T_DIM * K_DIM;
    float* vb    = gb   + (size_t)T_DIM * K_DIM;
    float* qa    = vb   + (size_t)T_DIM * V_DIM;
    float* kia   = qa   + (size_t)T_DIM * K_DIM;
    float* kh    = kia  + (size_t)T_DIM * K_DIM;
    float* opre  = kh   + (size_t)T_DIM * K_DIM;
    float* a15   = opre + (size_t)T_DIM * V_DIM;
    float* sdump = a15  + (size_t)NCHUNK * K_DIM;

    __half* hscr = 0;
    cudaGetSymbolAddress((void**)&hscr, g_scratch_h);
    __half* Xh    = hscr;
    __half* Wqh   = Xh    + (size_t)T_DIM * H_DIM;
    __half* Wkh   = Wqh   + (size_t)K_DIM * H_DIM;
    __half* Wgh   = Wkh   + (size_t)K_DIM * H_DIM;
    __half* Wvh   = Wgh   + (size_t)K_DIM * H_DIM;
    __half* Woh   = Wvh   + (size_t)K_DIM * H_DIM;
    __half* opreh = Woh   + (size_t)O_DIM * V_DIM;
    __half* qah   = opreh + (size_t)T_DIM * V_DIM;
    __half* snap  = qah   + (size_t)T_DIM * K_DIM;

    const size_t out_main = (size_t)T_DIM * O_DIM;
    const size_t out_full = out_main + (size_t)K_DIM * V_DIM;
    float* state_out = ((size_t)out_size >= out_full) ? (out + out_main) : sdump;

    dim3 blk(256);

    // one-time fp32->fp16 conversions
    f2h_kernel<<<2048, 256>>>(X,  Xh,  (int)((size_t)T_DIM * H_DIM / 4));
    f2h_kernel<<<1024, 256>>>(Wq, Wqh, (int)((size_t)K_DIM * H_DIM / 4));
    f2h_kernel<<<1024, 256>>>(Wk, Wkh, (int)((size_t)K_DIM * H_DIM / 4));
    f2h_kernel<<<1024, 256>>>(Wg, Wgh, (int)((size_t)K_DIM * H_DIM / 4));
    f2h_kernel<<<1024, 256>>>(Wv, Wvh, (int)((size_t)K_DIM * H_DIM / 4));
    f2h_kernel<<<1024, 256>>>(Wo, Woh, (int)((size_t)O_DIM * V_DIM / 4));

    // projections: q (linear), k (sigmoid), g (sigmoid), v (linear)
    gemm_h_nt<<<dim3(K_DIM / 128, T_DIM / 128), blk>>>(Xh, Wqh, bq, qb, T_DIM, K_DIM, H_DIM, 0);
    gemm_h_nt<<<dim3(K_DIM / 128, T_DIM / 128), blk>>>(Xh, Wkh, bk, kb, T_DIM, K_DIM, H_DIM, 1);
    gemm_h_nt<<<dim3(K_DIM / 128, T_DIM / 128), blk>>>(Xh, Wgh, bg, gb, T_DIM, K_DIM, H_DIM, 1);
    gemm_h_nt<<<dim3(V_DIM / 128, T_DIM / 128), blk>>>(Xh, Wvh, bv, vb, T_DIM, V_DIM, H_DIM, 0);

    // chunked gated-linear-attention pipeline
    prep_kernel<<<NCHUNK, blk>>>(qb, kb, gb, qa, qah, kia, kh, a15);
    intra_kernel<<<NCHUNK, blk>>>(qa, kia, vb, opre);
    serial_kernel<<<NCHUNK, blk>>>(kh, a15, vb, snap, state_out);
    inter_kernel<<<dim3(8, NCHUNK - 1), blk>>>(qah, snap, opre);

    // opre -> fp16, output projection
    f2h_kernel<<<1024, 256>>>(opre, opreh, (int)((size_t)T_DIM * V_DIM / 4));
    gemm_h_nt<<<dim3(O_DIM / 128, T_DIM / 128), blk>>>(opreh, Woh, bo, out, T_DIM, O_DIM, V_DIM, 0);
}

// round 9
// speedup vs baseline: 3.0178x; 1.6509x over previous
#include <cuda_runtime.h>
#include <cuda_fp16.h>
#include <math.h>
#include <stddef.h>
#include <stdint.h>

typedef unsigned long long ull;

#define T_DIM 4096
#define H_DIM 2048
#define K_DIM 1024
#define V_DIM 1024
#define O_DIM 2048
#define CHUNK 32
#define NCHUNK 128

// fp32 scratch: q | k | g | v | qa | kia | opre | a15 | sdump
__device__ __align__(16) float g_scratch[(size_t)5 * T_DIM * K_DIM +
                                         (size_t)2 * T_DIM * V_DIM +
                                         (size_t)NCHUNK * K_DIM +
                                         (size_t)K_DIM * V_DIM];
// fp16 scratch: Xh | Wqh | Wkh | Wgh | Wvh | Woh | opreh | qah | khT | vT | snap
__device__ __align__(16) __half g_scratch_h[(size_t)T_DIM * H_DIM +
                                            (size_t)4 * K_DIM * H_DIM +
                                            (size_t)O_DIM * V_DIM +
                                            (size_t)T_DIM * V_DIM +
                                            (size_t)3 * T_DIM * K_DIM +
                                            (size_t)NCHUNK * K_DIM * V_DIM];

// ---------------- tensor-core + cp.async helpers ----------------
__device__ __forceinline__ void ldm_x4(uint32_t* r, const __half* p) {
    uint32_t addr = (uint32_t)__cvta_generic_to_shared(p);
    asm volatile("ldmatrix.sync.aligned.m8n8.x4.shared.b16 {%0,%1,%2,%3}, [%4];"
                 : "=r"(r[0]), "=r"(r[1]), "=r"(r[2]), "=r"(r[3]) : "r"(addr));
}
__device__ __forceinline__ void mma16816(float* d, const uint32_t* a, const uint32_t* b) {
    asm volatile(
        "mma.sync.aligned.m16n8k16.row.col.f32.f16.f16.f32 "
        "{%0,%1,%2,%3}, {%4,%5,%6,%7}, {%8,%9}, {%0,%1,%2,%3};"
        : "+f"(d[0]), "+f"(d[1]), "+f"(d[2]), "+f"(d[3])
        : "r"(a[0]), "r"(a[1]), "r"(a[2]), "r"(a[3]), "r"(b[0]), "r"(b[1]));
}
__device__ __forceinline__ void cp_async16(__half* smem_dst, const __half* gsrc) {
    uint32_t d = (uint32_t)__cvta_generic_to_shared(smem_dst);
    asm volatile("cp.async.cg.shared.global [%0], [%1], 16;" :: "r"(d), "l"(gsrc));
}
#define CP_COMMIT() asm volatile("cp.async.commit_group;")
#define CP_WAIT(n)  asm volatile("cp.async.wait_group %0;" :: "n"(n))

// ---------------- fp32 -> fp16 convert ----------------
__global__ void f2h_kernel(const float* __restrict__ src, __half* __restrict__ dst, int n4)
{
    int i = blockIdx.x * blockDim.x + threadIdx.x;
    const int stride = gridDim.x * blockDim.x;
    for (; i < n4; i += stride) {
        float4 v = ((const float4*)src)[i];
        __half2 h0 = __floats2half2_rn(v.x, v.y);
        __half2 h1 = __floats2half2_rn(v.z, v.w);
        uint2 u;
        u.x = *reinterpret_cast<unsigned*>(&h0);
        u.y = *reinterpret_cast<unsigned*>(&h1);
        ((uint2*)dst)[i] = u;
    }
}

// ---------------- fp16 NT GEMM (proven R4 kernel, unchanged) ----------------
#define KP 40
__global__ void __launch_bounds__(256, 2) gemm_h_nt(
    const __half* __restrict__ A, const __half* __restrict__ B,
    const float* __restrict__ bias, float* __restrict__ C,
    int M, int N, int Kd, int act)
{
    __shared__ __half As[2][128 * KP];
    __shared__ __half Bs[2][128 * KP];

    const int tid = threadIdx.x;
    const int lane = tid & 31;
    const int wid = tid >> 5;
    const int warpM = wid >> 2;
    const int warpN = wid & 3;
    const int bm = blockIdx.y * 128;
    const int bn = blockIdx.x * 128;

    float acc[4][4][4];
#pragma unroll
    for (int a = 0; a < 4; a++)
#pragma unroll
        for (int b = 0; b < 4; b++)
#pragma unroll
            for (int c = 0; c < 4; c++) acc[a][b][c] = 0.f;

    const int iters = Kd / 32;

#define LOAD_TILE(buf, k0)                                                     \
    {                                                                          \
        _Pragma("unroll")                                                      \
        for (int p = 0; p < 2; p++) {                                          \
            const int c = tid + p * 256;                                       \
            const int row = c >> 2;                                            \
            const int col = (c & 3) * 8;                                       \
            cp_async16(&As[buf][row * KP + col],                               \
                       A + (size_t)(bm + row) * Kd + (k0) + col);              \
            cp_async16(&Bs[buf][row * KP + col],                               \
                       B + (size_t)(bn + row) * Kd + (k0) + col);              \
        }                                                                      \
    }

    LOAD_TILE(0, 0);
    CP_COMMIT();

    for (int it = 0; it < iters; ++it) {
        if (it + 1 < iters) {
            LOAD_TILE((it + 1) & 1, (it + 1) * 32);
            CP_COMMIT();
            CP_WAIT(1);
        } else {
            CP_WAIT(0);
        }
        __syncthreads();

        const __half* Ab = As[it & 1];
        const __half* Bb = Bs[it & 1];
#pragma unroll
        for (int ks = 0; ks < 2; ks++) {
            const int k0 = ks * 16;
            uint32_t afr[4][4];
            uint32_t bfr[4][2];
#pragma unroll
            for (int fm = 0; fm < 4; fm++) {
                const __half* p = &Ab[(warpM * 64 + fm * 16 + (lane & 7) +
                                       ((lane >> 3) & 1) * 8) * KP +
                                      k0 + (lane >> 4) * 8];
                ldm_x4(afr[fm], p);
            }
#pragma unroll
            for (int fp = 0; fp < 2; fp++) {
                uint32_t r[4];
                const __half* p = &Bb[(warpN * 32 + fp * 16 + (lane & 7) +
                                       (lane >> 4) * 8) * KP +
                                      k0 + ((lane >> 3) & 1) * 8];
                ldm_x4(r, p);
                bfr[2 * fp][0] = r[0];     bfr[2 * fp][1] = r[1];
                bfr[2 * fp + 1][0] = r[2]; bfr[2 * fp + 1][1] = r[3];
            }
#pragma unroll
            for (int fm = 0; fm < 4; fm++)
#pragma unroll
                for (int fn = 0; fn < 4; fn++)
                    mma16816(acc[fm][fn], afr[fm], bfr[fn]);
        }
        __syncthreads();
    }
#undef LOAD_TILE

#pragma unroll
    for (int fm = 0; fm < 4; fm++)
#pragma unroll
        for (int fn = 0; fn < 4; fn++)
#pragma unroll
            for (int h = 0; h < 2; h++) {
                const int row = bm + warpM * 64 + fm * 16 + (lane >> 2) + h * 8;
                const int col = bn + warpN * 32 + fn * 8 + (lane & 3) * 2;
                float c0 = acc[fm][fn][2 * h]     + __ldg(&bias[col]);
                float c1 = acc[fm][fn][2 * h + 1] + __ldg(&bias[col + 1]);
                if (act) {
                    c0 = 1.f / (1.f + expf(-c0));
                    c1 = 1.f / (1.f + expf(-c1));
                }
                *(float2*)(C + (size_t)row * N + col) = make_float2(c0, c1);
            }
}

// ---------------- prep: per-chunk cumulative gates ----------------
// A_u[k] = prod_{r<=u} g_r[k]. Emits:
//   qa  = q * A_u (fp32), qah = fp16(qa), kia = k / A_u (fp32 IEEE div)
//   a15 = A_31 per chunk
//   khT[cid][k][step] = fp16(kia * A_31)   (transposed, step-contiguous)
//   vT [cid][v][step] = fp16(v)            (transposed, step-contiguous)
__global__ void __launch_bounds__(256) prep_kernel(
    const float* __restrict__ q, const float* __restrict__ kk,
    const float* __restrict__ g, const float* __restrict__ vv,
    float* __restrict__ qa, __half* __restrict__ qah,
    float* __restrict__ kia, float* __restrict__ a15,
    __half* __restrict__ khT, __half* __restrict__ vT)
{
    const int cid = blockIdx.x;
    const int kc = threadIdx.x * 4;
    const size_t t0 = (size_t)cid * CHUNK;
    float4 A = make_float4(1.f, 1.f, 1.f, 1.f);
#pragma unroll 4
    for (int u = 0; u < CHUNK; u++) {
        const size_t off = (t0 + u) * K_DIM + kc;
        float4 gv = *(const float4*)(g + off);
        A.x *= gv.x; A.y *= gv.y; A.z *= gv.z; A.w *= gv.w;
        float4 qv = *(const float4*)(q + off);
        float4 qa4 = make_float4(qv.x * A.x, qv.y * A.y, qv.z * A.z, qv.w * A.w);
        *(float4*)(qa + off) = qa4;
        __half2 h0 = __floats2half2_rn(qa4.x, qa4.y);
        __half2 h1 = __floats2half2_rn(qa4.z, qa4.w);
        uint2 uu; uu.x = *(unsigned*)&h0; uu.y = *(unsigned*)&h1;
        *(uint2*)(qah + off) = uu;
        float4 kv = *(const float4*)(kk + off);
        float4 ki = make_float4(__fdiv_rn(kv.x, A.x), __fdiv_rn(kv.y, A.y),
                                __fdiv_rn(kv.z, A.z), __fdiv_rn(kv.w, A.w));
        *(float4*)(kia + off) = ki;
    }
    *(float4*)(a15 + (size_t)cid * K_DIM + kc) = A;

    // khT: rows kc..kc+3 (k index), 32 steps contiguous, fp16
    {
        uint32_t buf[4][16];
        float prev[4];
#pragma unroll
        for (int u = 0; u < CHUNK; u++) {
            const size_t off = (t0 + u) * K_DIM + kc;
            float4 ki = *(const float4*)(kia + off);
            float cur[4] = {ki.x * A.x, ki.y * A.y, ki.z * A.z, ki.w * A.w};
            if (u & 1) {
#pragma unroll
                for (int j = 0; j < 4; j++) {
                    __half2 h = __floats2half2_rn(prev[j], cur[j]);
                    buf[j][u >> 1] = *(unsigned*)&h;
                }
            } else {
#pragma unroll
                for (int j = 0; j < 4; j++) prev[j] = cur[j];
            }
        }
#pragma unroll
        for (int j = 0; j < 4; j++) {
            __half* dst = khT + ((size_t)cid * K_DIM + kc + j) * CHUNK;
#pragma unroll
            for (int c = 0; c < 4; c++)
                *(uint4*)(dst + c * 8) = *(uint4*)&buf[j][c * 4];
        }
    }
    // vT: rows kc..kc+3 (v index), 32 steps contiguous, fp16
    {
        uint32_t buf[4][16];
        float prev[4];
#pragma unroll
        for (int u = 0; u < CHUNK; u++) {
            float4 v4 = *(const float4*)(vv + (t0 + u) * V_DIM + kc);
            float cur[4] = {v4.x, v4.y, v4.z, v4.w};
            if (u & 1) {
#pragma unroll
                for (int j = 0; j < 4; j++) {
                    __half2 h = __floats2half2_rn(prev[j], cur[j]);
                    buf[j][u >> 1] = *(unsigned*)&h;
                }
            } else {
#pragma unroll
                for (int j = 0; j < 4; j++) prev[j] = cur[j];
            }
        }
#pragma unroll
        for (int j = 0; j < 4; j++) {
            __half* dst = vT + ((size_t)cid * V_DIM + kc + j) * CHUNK;
#pragma unroll
            for (int c = 0; c < 4; c++)
                *(uint4*)(dst + c * 8) = *(uint4*)&buf[j][c * 4];
        }
    }
}

// ---------------- intra-chunk: P = QA @ KIA^T (masked), out = P @ V ----------
#define TS 128
__global__ void __launch_bounds__(256) intra_kernel(
    const float* __restrict__ qa, const float* __restrict__ kia,
    const float* __restrict__ vv, float* __restrict__ opre)
{
    __shared__ float qs[CHUNK][TS + 4];
    __shared__ float ks_[CHUNK][TS + 4];
    __shared__ float Ps[CHUNK][CHUNK + 1];
    const int tid = threadIdx.x;
    const int cid = blockIdx.x;
    const size_t t0 = (size_t)cid * CHUNK;

    for (int i = tid; i < CHUNK * (CHUNK + 1); i += 256)
        ((float*)Ps)[i] = 0.f;

    const int u0 = ((tid >> 2) & 3) * 8;
    const int s0 = (tid & 3) * 8;
    const int ksl = tid >> 4;
    float acc[8][8];
#pragma unroll
    for (int i = 0; i < 8; i++)
#pragma unroll
        for (int j = 0; j < 8; j++) acc[i][j] = 0.f;

    for (int kt = 0; kt < K_DIM; kt += TS) {
        __syncthreads();
#pragma unroll
        for (int p = 0; p < 4; p++) {
            int idx = tid + p * 256;
            int rr = idx >> 5;
            int cc = (idx & 31) * 4;
            *(float4*)&qs[rr][cc]  = *(const float4*)(qa  + (t0 + rr) * K_DIM + kt + cc);
            *(float4*)&ks_[rr][cc] = *(const float4*)(kia + (t0 + rr) * K_DIM + kt + cc);
        }
        __syncthreads();
        const int kb = ksl * 8;
#pragma unroll
        for (int km = 0; km < 8; km++) {
            const int kx = kb + km;
            float qv[8], kv[8];
#pragma unroll
            for (int i = 0; i < 8; i++) qv[i] = qs[u0 + i][kx];
#pragma unroll
            for (int j = 0; j < 8; j++) kv[j] = ks_[s0 + j][kx];
#pragma unroll
            for (int i = 0; i < 8; i++)
#pragma unroll
                for (int j = 0; j < 8; j++)
                    acc[i][j] = fmaf(qv[i], kv[j], acc[i][j]);
        }
    }
    __syncthreads();
#pragma unroll
    for (int i = 0; i < 8; i++)
#pragma unroll
        for (int j = 0; j < 8; j++)
            atomicAdd(&Ps[u0 + i][s0 + j], acc[i][j]);
    __syncthreads();

    const int vc = tid * 4;
#pragma unroll
    for (int pass = 0; pass < 4; pass++) {
        float o[8][4];
#pragma unroll
        for (int i = 0; i < 8; i++) { o[i][0] = o[i][1] = o[i][2] = o[i][3] = 0.f; }
        for (int s = 0; s < CHUNK; s++) {
            float4 v4 = *(const float4*)(vv + (t0 + s) * V_DIM + vc);
#pragma unroll
            for (int i = 0; i < 8; i++) {
                const int u = pass * 8 + i;
                float p = (s <= u) ? Ps[u][s] : 0.f;
                o[i][0] = fmaf(p, v4.x, o[i][0]);
                o[i][1] = fmaf(p, v4.y, o[i][1]);
                o[i][2] = fmaf(p, v4.z, o[i][2]);
                o[i][3] = fmaf(p, v4.w, o[i][3]);
            }
        }
#pragma unroll
        for (int i = 0; i < 8; i++) {
            const int u = pass * 8 + i;
            *(float4*)(opre + (t0 + u) * V_DIM + vc) =
                make_float4(o[i][0], o[i][1], o[i][2], o[i][3]);
        }
    }
}

// ---------------- serial v2: tensor-core rank-32 state updates --------------
// 128 CTAs = 4 kg x 32 vs; warp owns 32 K-rows x 32 V-cols of state in mma
// fp32 accumulators (2 m16-tiles x 4 n8-tiles). Per chunk:
//   1) snapshot acc -> smem fp16 [v][k] -> coalesced global snap[cid][v][k]
//   2) decay acc by a15 (smem-staged)
//   3) cp.async khT/vT tiles (issued early, hidden under snapshot write)
//   4) 4 ldmatrix + 16 mma per warp  (S += K̂^T V)
__global__ void __launch_bounds__(256, 1) serial_kernel2(
    const __half* __restrict__ khT, const __half* __restrict__ vT,
    const float* __restrict__ a15, __half* __restrict__ snap,
    float* __restrict__ state_out)
{
    __shared__ __half khs[256 * KP];
    __shared__ __half vs[32 * KP];
    __shared__ __half snapS[32 * 264];
    __shared__ float a15s[256];

    const int tid = threadIdx.x;
    const int lane = tid & 31;
    const int wid = tid >> 5;
    const int kg = blockIdx.x & 3;
    const int vsb = blockIdx.x >> 2;
    const int kbaseCTA = kg * 256;
    const int vbase = vsb * 32;

    float acc[2][4][4];
#pragma unroll
    for (int mt = 0; mt < 2; mt++)
#pragma unroll
        for (int nt = 0; nt < 4; nt++)
#pragma unroll
            for (int c = 0; c < 4; c++) acc[mt][nt][c] = 0.f;

    for (int cid = 0; cid < NCHUNK; cid++) {
        // 1. snapshot acc -> snapS (fp16, [v][k] with pitch 264); stage a15
#pragma unroll
        for (int mt = 0; mt < 2; mt++)
#pragma unroll
            for (int nt = 0; nt < 4; nt++)
#pragma unroll
                for (int h = 0; h < 2; h++) {
                    const int row = wid * 32 + mt * 16 + (lane >> 2) + h * 8;
                    const int col = nt * 8 + (lane & 3) * 2;
                    snapS[col * 264 + row]       = __float2half(acc[mt][nt][2 * h]);
                    snapS[(col + 1) * 264 + row] = __float2half(acc[mt][nt][2 * h + 1]);
                }
        a15s[tid] = a15[(size_t)cid * K_DIM + kbaseCTA + tid];
        __syncthreads();   // closes prev chunk's ldm reads; publishes snapS/a15s

        // 2. cp.async this chunk's tiles (khs/vs free now)
        {
            const __half* kSrc = khT + ((size_t)cid * K_DIM + kbaseCTA) * CHUNK;
#pragma unroll
            for (int p = 0; p < 4; p++) {
                const int idx = tid + p * 256;
                const int row = idx >> 2;
                const int c = (idx & 3) * 8;
                cp_async16(&khs[row * KP + c], kSrc + row * CHUNK + c);
            }
            if (tid < 128) {
                const int row = tid >> 2;
                const int c = (tid & 3) * 8;
                cp_async16(&vs[row * KP + c],
                           vT + ((size_t)cid * V_DIM + vbase + row) * CHUNK + c);
            }
            CP_COMMIT();
        }

        // 3. snapshot -> global (coalesced 16B chunks)
#pragma unroll
        for (int p = 0; p < 4; p++) {
            const int idx = tid + p * 256;
            const int vr = idx >> 5;
            const int kc16 = idx & 31;
            uint4 val = *(uint4*)&snapS[vr * 264 + kc16 * 8];
            *(uint4*)(snap + ((size_t)cid * V_DIM + vbase + vr) * K_DIM +
                      kbaseCTA + kc16 * 8) = val;
        }

        // 4. decay
#pragma unroll
        for (int mt = 0; mt < 2; mt++)
#pragma unroll
            for (int h = 0; h < 2; h++) {
                const float av = a15s[wid * 32 + mt * 16 + (lane >> 2) + h * 8];
#pragma unroll
                for (int nt = 0; nt < 4; nt++) {
                    acc[mt][nt][2 * h]     *= av;
                    acc[mt][nt][2 * h + 1] *= av;
                }
            }

        // 5. wait tiles; also fences snapS reads before next-chunk writes
        CP_WAIT(0);
        __syncthreads();

        // 6. S += K̂^T V  (2 k16 halves)
#pragma unroll
        for (int ks = 0; ks < 2; ks++) {
            const int k0 = ks * 16;
            uint32_t afr[2][4];
            uint32_t bfr[4][2];
#pragma unroll
            for (int mt = 0; mt < 2; mt++) {
                const __half* p = &khs[(wid * 32 + mt * 16 + (lane & 7) +
                                        ((lane >> 3) & 1) * 8) * KP +
                                       k0 + (lane >> 4) * 8];
                ldm_x4(afr[mt], p);
            }
#pragma unroll
            for (int fp = 0; fp < 2; fp++) {
                uint32_t r[4];
                const __half* p = &vs[(fp * 16 + (lane & 7) + (lane >> 4) * 8) * KP +
                                      k0 + ((lane >> 3) & 1) * 8];
                ldm_x4(r, p);
                bfr[2 * fp][0] = r[0];     bfr[2 * fp][1] = r[1];
                bfr[2 * fp + 1][0] = r[2]; bfr[2 * fp + 1][1] = r[3];
            }
#pragma unroll
            for (int mt = 0; mt < 2; mt++)
#pragma unroll
                for (int nt = 0; nt < 4; nt++)
                    mma16816(acc[mt][nt], afr[mt], bfr[nt]);
        }
    }

    // final state (fp32, [k][v] row-major)
#pragma unroll
    for (int mt = 0; mt < 2; mt++)
#pragma unroll
        for (int nt = 0; nt < 4; nt++)
#pragma unroll
            for (int h = 0; h < 2; h++) {
                const int row = kbaseCTA + wid * 32 + mt * 16 + (lane >> 2) + h * 8;
                const int col = vbase + nt * 8 + (lane & 3) * 2;
                *(float2*)(state_out + (size_t)row * V_DIM + col) =
                    make_float2(acc[mt][nt][2 * h], acc[mt][nt][2 * h + 1]);
            }
}

// ---------------- inter: opre += qa_chunk @ snapshot^T (tensor cores) -------
__global__ void __launch_bounds__(256) inter_kernel(
    const __half* __restrict__ qah, const __half* __restrict__ snap,
    float* __restrict__ opre)
{
    __shared__ __half As[2][32 * KP];
    __shared__ __half Bs[2][128 * KP];
    const int tid = threadIdx.x;
    const int lane = tid & 31;
    const int wid = tid >> 5;
    const int warpM = wid >> 2;
    const int warpN = wid & 3;
    const int vt = blockIdx.x;
    const int cid = blockIdx.y + 1;

    const __half* A = qah + (size_t)cid * CHUNK * K_DIM;
    const __half* B = snap + ((size_t)cid * V_DIM + vt * 128) * K_DIM;

    float acc[4][4];
#pragma unroll
    for (int a = 0; a < 4; a++)
#pragma unroll
        for (int c = 0; c < 4; c++) acc[a][c] = 0.f;

#define LOAD_TILE_I(buf, k0)                                                   \
    {                                                                          \
        if (tid < 128) {                                                       \
            const int row = tid >> 2;                                          \
            const int col = (tid & 3) * 8;                                     \
            cp_async16(&As[buf][row * KP + col],                               \
                       A + (size_t)row * K_DIM + (k0) + col);                  \
        }                                                                      \
        _Pragma("unroll")                                                      \
        for (int p = 0; p < 2; p++) {                                          \
            const int c = tid + p * 256;                                       \
            const int row = c >> 2;                                            \
            const int col = (c & 3) * 8;                                       \
            cp_async16(&Bs[buf][row * KP + col],                               \
                       B + (size_t)row * K_DIM + (k0) + col);                  \
        }                                                                      \
    }

    LOAD_TILE_I(0, 0);
    CP_COMMIT();
    const int iters = K_DIM / 32;
    for (int it = 0; it < iters; ++it) {
        if (it + 1 < iters) {
            LOAD_TILE_I((it + 1) & 1, (it + 1) * 32);
            CP_COMMIT();
            CP_WAIT(1);
        } else {
            CP_WAIT(0);
        }
        __syncthreads();
        const __half* Ab = As[it & 1];
        const __half* Bb = Bs[it & 1];
#pragma unroll
        for (int ks = 0; ks < 2; ks++) {
            const int k0 = ks * 16;
            uint32_t afr[4];
            uint32_t bfr[4][2];
            {
                const __half* p = &Ab[(warpM * 16 + (lane & 7) +
                                       ((lane >> 3) & 1) * 8) * KP +
                                      k0 + (lane >> 4) * 8];
                ldm_x4(afr, p);
            }
#pragma unroll
            for (int fp = 0; fp < 2; fp++) {
                uint32_t r[4];
                const __half* p = &Bb[(warpN * 32 + fp * 16 + (lane & 7) +
                                       (lane >> 4) * 8) * KP +
                                      k0 + ((lane >> 3) & 1) * 8];
                ldm_x4(r, p);
                bfr[2 * fp][0] = r[0];     bfr[2 * fp][1] = r[1];
                bfr[2 * fp + 1][0] = r[2]; bfr[2 * fp + 1][1] = r[3];
            }
#pragma unroll
            for (int fn = 0; fn < 4; fn++) mma16816(acc[fn], afr, bfr[fn]);
        }
        __syncthreads();
    }
#undef LOAD_TILE_I

#pragma unroll
    for (int fn = 0; fn < 4; fn++)
#pragma unroll
        for (int h = 0; h < 2; h++) {
            const int row = cid * CHUNK + warpM * 16 + (lane >> 2) + h * 8;
            const int col = vt * 128 + warpN * 32 + fn * 8 + (lane & 3) * 2;
            float2 o = *(float2*)(opre + (size_t)row * V_DIM + col);
            o.x += acc[fn][2 * h];
            o.y += acc[fn][2 * h + 1];
            *(float2*)(opre + (size_t)row * V_DIM + col) = o;
        }
}

// ---------------------------------------------------------------------------
extern "C" void kernel_launch(void* const* d_in, const int* in_sizes, int n_in,
                              void* d_out, int out_size)
{
    const float* X  = (const float*)d_in[0];
    const float* Wq = (const float*)d_in[1];
    const float* bq = (const float*)d_in[2];
    const float* Wk = (const float*)d_in[3];
    const float* bk = (const float*)d_in[4];
    const float* Wv = (const float*)d_in[5];
    const float* bv = (const float*)d_in[6];
    const float* Wg = (const float*)d_in[7];
    const float* bg = (const float*)d_in[8];
    const float* Wo = (const float*)d_in[9];
    const float* bo = (const float*)d_in[10];
    float* out = (float*)d_out;

    float* scratch = 0;
    cudaGetSymbolAddress((void**)&scratch, g_scratch);
    float* qb    = scratch;
    float* kb    = qb   + (size_t)T_DIM * K_DIM;
    float* gb    = kb   + (size_t)T_DIM * K_DIM;
    float* vb    = gb   + (size_t)T_DIM * K_DIM;
    float* qa    = vb   + (size_t)T_DIM * V_DIM;
    float* kia   = qa   + (size_t)T_DIM * K_DIM;
    float* opre  = kia  + (size_t)T_DIM * K_DIM;
    float* a15   = opre + (size_t)T_DIM * V_DIM;
    float* sdump = a15  + (size_t)NCHUNK * K_DIM;

    __half* hscr = 0;
    cudaGetSymbolAddress((void**)&hscr, g_scratch_h);
    __half* Xh    = hscr;
    __half* Wqh   = Xh    + (size_t)T_DIM * H_DIM;
    __half* Wkh   = Wqh   + (size_t)K_DIM * H_DIM;
    __half* Wgh   = Wkh   + (size_t)K_DIM * H_DIM;
    __half* Wvh   = Wgh   + (size_t)K_DIM * H_DIM;
    __half* Woh   = Wvh   + (size_t)K_DIM * H_DIM;
    __half* opreh = Woh   + (size_t)O_DIM * V_DIM;
    __half* qah   = opreh + (size_t)T_DIM * V_DIM;
    __half* khT   = qah   + (size_t)T_DIM * K_DIM;
    __half* vT    = khT   + (size_t)T_DIM * K_DIM;
    __half* snap  = vT    + (size_t)T_DIM * K_DIM;

    const size_t out_main = (size_t)T_DIM * O_DIM;
    const size_t out_full = out_main + (size_t)K_DIM * V_DIM;
    float* state_out = ((size_t)out_size >= out_full) ? (out + out_main) : sdump;

    dim3 blk(256);

    // one-time fp32->fp16 conversions
    f2h_kernel<<<2048, 256>>>(X,  Xh,  (int)((size_t)T_DIM * H_DIM / 4));
    f2h_kernel<<<1024, 256>>>(Wq, Wqh, (int)((size_t)K_DIM * H_DIM / 4));
    f2h_kernel<<<1024, 256>>>(Wk, Wkh, (int)((size_t)K_DIM * H_DIM / 4));
    f2h_kernel<<<1024, 256>>>(Wg, Wgh, (int)((size_t)K_DIM * H_DIM / 4));
    f2h_kernel<<<1024, 256>>>(Wv, Wvh, (int)((size_t)K_DIM * H_DIM / 4));
    f2h_kernel<<<1024, 256>>>(Wo, Woh, (int)((size_t)O_DIM * V_DIM / 4));

    // projections: q (linear), k (sigmoid), g (sigmoid), v (linear)
    gemm_h_nt<<<dim3(K_DIM / 128, T_DIM / 128), blk>>>(Xh, Wqh, bq, qb, T_DIM, K_DIM, H_DIM, 0);
    gemm_h_nt<<<dim3(K_DIM / 128, T_DIM / 128), blk>>>(Xh, Wkh, bk, kb, T_DIM, K_DIM, H_DIM, 1);
    gemm_h_nt<<<dim3(K_DIM / 128, T_DIM / 128), blk>>>(Xh, Wgh, bg, gb, T_DIM, K_DIM, H_DIM, 1);
    gemm_h_nt<<<dim3(V_DIM / 128, T_DIM / 128), blk>>>(Xh, Wvh, bv, vb, T_DIM, V_DIM, H_DIM, 0);

    // chunked gated-linear-attention pipeline
    prep_kernel<<<NCHUNK, blk>>>(qb, kb, gb, vb, qa, qah, kia, a15, khT, vT);
    intra_kernel<<<NCHUNK, blk>>>(qa, kia, vb, opre);
    serial_kernel2<<<NCHUNK, blk>>>(khT, vT, a15, snap, state_out);
    inter_kernel<<<dim3(8, NCHUNK - 1), blk>>>(qah, snap, opre);

    // opre -> fp16, output projection
    f2h_kernel<<<1024, 256>>>(opre, opreh, (int)((size_t)T_DIM * V_DIM / 4));
    gemm_h_nt<<<dim3(O_DIM / 128, T_DIM / 128), blk>>>(opreh, Woh, bo, out, T_DIM, O_DIM, V_DIM, 0);
}

// round 10
// speedup vs baseline: 3.2501x; 1.0770x over previous
#include <cuda_runtime.h>
#include <cuda_fp16.h>
#include <math.h>
#include <stddef.h>
#include <stdint.h>

typedef unsigned long long ull;

#define T_DIM 4096
#define H_DIM 2048
#define K_DIM 1024
#define V_DIM 1024
#define O_DIM 2048
#define CHUNK 32
#define NCHUNK 128

// fp32 scratch: q | k | g | v | qa | kia | opre | a15 | sdump
__device__ __align__(16) float g_scratch[(size_t)5 * T_DIM * K_DIM +
                                         (size_t)2 * T_DIM * V_DIM +
                                         (size_t)NCHUNK * K_DIM +
                                         (size_t)K_DIM * V_DIM];
// fp16 scratch: Xh | Wqh | Wkh | Wgh | Wvh | Woh | opreh | qah | khT | vT | snap
__device__ __align__(16) __half g_scratch_h[(size_t)T_DIM * H_DIM +
                                            (size_t)4 * K_DIM * H_DIM +
                                            (size_t)O_DIM * V_DIM +
                                            (size_t)T_DIM * V_DIM +
                                            (size_t)3 * T_DIM * K_DIM +
                                            (size_t)NCHUNK * K_DIM * V_DIM];

// ---------------- tensor-core + cp.async helpers ----------------
__device__ __forceinline__ void ldm_x4(uint32_t* r, const __half* p) {
    uint32_t addr = (uint32_t)__cvta_generic_to_shared(p);
    asm volatile("ldmatrix.sync.aligned.m8n8.x4.shared.b16 {%0,%1,%2,%3}, [%4];"
                 : "=r"(r[0]), "=r"(r[1]), "=r"(r[2]), "=r"(r[3]) : "r"(addr));
}
__device__ __forceinline__ void mma16816(float* d, const uint32_t* a, const uint32_t* b) {
    asm volatile(
        "mma.sync.aligned.m16n8k16.row.col.f32.f16.f16.f32 "
        "{%0,%1,%2,%3}, {%4,%5,%6,%7}, {%8,%9}, {%0,%1,%2,%3};"
        : "+f"(d[0]), "+f"(d[1]), "+f"(d[2]), "+f"(d[3])
        : "r"(a[0]), "r"(a[1]), "r"(a[2]), "r"(a[3]), "r"(b[0]), "r"(b[1]));
}
__device__ __forceinline__ void cp_async16(__half* smem_dst, const __half* gsrc) {
    uint32_t d = (uint32_t)__cvta_generic_to_shared(smem_dst);
    asm volatile("cp.async.cg.shared.global [%0], [%1], 16;" :: "r"(d), "l"(gsrc));
}
#define CP_COMMIT() asm volatile("cp.async.commit_group;")
#define CP_WAIT(n)  asm volatile("cp.async.wait_group %0;" :: "n"(n))

// ---------------- fp32 -> fp16 convert (single + batched x4) ----------------
__global__ void f2h_kernel(const float* __restrict__ src, __half* __restrict__ dst, int n4)
{
    int i = blockIdx.x * blockDim.x + threadIdx.x;
    const int stride = gridDim.x * blockDim.x;
    for (; i < n4; i += stride) {
        float4 v = ((const float4*)src)[i];
        __half2 h0 = __floats2half2_rn(v.x, v.y);
        __half2 h1 = __floats2half2_rn(v.z, v.w);
        uint2 u;
        u.x = *reinterpret_cast<unsigned*>(&h0);
        u.y = *reinterpret_cast<unsigned*>(&h1);
        ((uint2*)dst)[i] = u;
    }
}
__global__ void f2h4_kernel(const float* __restrict__ s0, const float* __restrict__ s1,
                            const float* __restrict__ s2, const float* __restrict__ s3,
                            __half* __restrict__ dst, int n4)
{
    const float* src = (blockIdx.y == 0) ? s0 : (blockIdx.y == 1) ? s1
                       : (blockIdx.y == 2) ? s2 : s3;
    __half* d = dst + (size_t)blockIdx.y * (size_t)n4 * 4;
    int i = blockIdx.x * blockDim.x + threadIdx.x;
    const int stride = gridDim.x * blockDim.x;
    for (; i < n4; i += stride) {
        float4 v = ((const float4*)src)[i];
        __half2 h0 = __floats2half2_rn(v.x, v.y);
        __half2 h1 = __floats2half2_rn(v.z, v.w);
        uint2 u;
        u.x = *reinterpret_cast<unsigned*>(&h0);
        u.y = *reinterpret_cast<unsigned*>(&h1);
        ((uint2*)d)[i] = u;
    }
}

// ---------------- fp16 NT GEMM core (proven R4 fragment patterns) -----------
#define KP 40
struct EpiPlain {
    const float* bias; float* C; int N; int act;
    __device__ __forceinline__ void store(int row, int col, float c0, float c1) const {
        c0 += __ldg(&bias[col]); c1 += __ldg(&bias[col + 1]);
        if (act) { c0 = 1.f / (1.f + expf(-c0)); c1 = 1.f / (1.f + expf(-c1)); }
        *(float2*)(C + (size_t)row * N + col) = make_float2(c0, c1);
    }
};
// routed epilogue: col>>10 selects one of 4 outputs (k,g get sigmoid)
struct EpiRoute {
    const float* b0; const float* b1; const float* b2; const float* b3;
    float* d0; float* d1; float* d2; float* d3;
    __device__ __forceinline__ void store(int row, int col, float c0, float c1) const {
        const int sel = col >> 10;
        const int lc = col & 1023;
        const float* bias = (sel == 0) ? b0 : (sel == 1) ? b1 : (sel == 2) ? b2 : b3;
        float* C = (sel == 0) ? d0 : (sel == 1) ? d1 : (sel == 2) ? d2 : d3;
        c0 += __ldg(&bias[lc]); c1 += __ldg(&bias[lc + 1]);
        if (sel == 1 || sel == 2) {
            c0 = 1.f / (1.f + expf(-c0)); c1 = 1.f / (1.f + expf(-c1));
        }
        *(float2*)(C + (size_t)row * 1024 + lc) = make_float2(c0, c1);
    }
};

template <class Epi>
__device__ __forceinline__ void gemm_body(
    const __half* __restrict__ A, const __half* __restrict__ B,
    int Kd, int bm, int bn, const Epi& epi)
{
    __shared__ __half As[2][128 * KP];
    __shared__ __half Bs[2][128 * KP];

    const int tid = threadIdx.x;
    const int lane = tid & 31;
    const int wid = tid >> 5;
    const int warpM = wid >> 2;
    const int warpN = wid & 3;

    float acc[4][4][4];
#pragma unroll
    for (int a = 0; a < 4; a++)
#pragma unroll
        for (int b = 0; b < 4; b++)
#pragma unroll
            for (int c = 0; c < 4; c++) acc[a][b][c] = 0.f;

    const int iters = Kd / 32;

#define LOAD_TILE(buf, k0)                                                     \
    {                                                                          \
        _Pragma("unroll")                                                      \
        for (int p = 0; p < 2; p++) {                                          \
            const int c = tid + p * 256;                                       \
            const int row = c >> 2;                                            \
            const int col = (c & 3) * 8;                                       \
            cp_async16(&As[buf][row * KP + col],                               \
                       A + (size_t)(bm + row) * Kd + (k0) + col);              \
            cp_async16(&Bs[buf][row * KP + col],                               \
                       B + (size_t)(bn + row) * Kd + (k0) + col);              \
        }                                                                      \
    }

    LOAD_TILE(0, 0);
    CP_COMMIT();

    for (int it = 0; it < iters; ++it) {
        if (it + 1 < iters) {
            LOAD_TILE((it + 1) & 1, (it + 1) * 32);
            CP_COMMIT();
            CP_WAIT(1);
        } else {
            CP_WAIT(0);
        }
        __syncthreads();

        const __half* Ab = As[it & 1];
        const __half* Bb = Bs[it & 1];
#pragma unroll
        for (int ks = 0; ks < 2; ks++) {
            const int k0 = ks * 16;
            uint32_t afr[4][4];
            uint32_t bfr[4][2];
#pragma unroll
            for (int fm = 0; fm < 4; fm++) {
                const __half* p = &Ab[(warpM * 64 + fm * 16 + (lane & 7) +
                                       ((lane >> 3) & 1) * 8) * KP +
                                      k0 + (lane >> 4) * 8];
                ldm_x4(afr[fm], p);
            }
#pragma unroll
            for (int fp = 0; fp < 2; fp++) {
                uint32_t r[4];
                const __half* p = &Bb[(warpN * 32 + fp * 16 + (lane & 7) +
                                       (lane >> 4) * 8) * KP +
                                      k0 + ((lane >> 3) & 1) * 8];
                ldm_x4(r, p);
                bfr[2 * fp][0] = r[0];     bfr[2 * fp][1] = r[1];
                bfr[2 * fp + 1][0] = r[2]; bfr[2 * fp + 1][1] = r[3];
            }
#pragma unroll
            for (int fm = 0; fm < 4; fm++)
#pragma unroll
                for (int fn = 0; fn < 4; fn++)
                    mma16816(acc[fm][fn], afr[fm], bfr[fn]);
        }
        __syncthreads();
    }
#undef LOAD_TILE

#pragma unroll
    for (int fm = 0; fm < 4; fm++)
#pragma unroll
        for (int fn = 0; fn < 4; fn++)
#pragma unroll
            for (int h = 0; h < 2; h++) {
                const int row = bm + warpM * 64 + fm * 16 + (lane >> 2) + h * 8;
                const int col = bn + warpN * 32 + fn * 8 + (lane & 3) * 2;
                epi.store(row, col, acc[fm][fn][2 * h], acc[fm][fn][2 * h + 1]);
            }
}

__global__ void __launch_bounds__(256, 2) gemm_h_nt(
    const __half* __restrict__ A, const __half* __restrict__ B,
    const float* __restrict__ bias, float* __restrict__ C,
    int M, int N, int Kd, int act)
{
    EpiPlain epi{bias, C, N, act};
    gemm_body(A, B, Kd, blockIdx.y * 128, blockIdx.x * 128, epi);
}

// merged 4-projection GEMM: B = stacked [Wq;Wk;Wg;Wv] (4096 x 2048), routed epi
__global__ void __launch_bounds__(256, 2) gemm_h_nt_proj(
    const __half* __restrict__ A, const __half* __restrict__ Wall,
    const float* bq, const float* bk, const float* bg, const float* bv,
    float* qb, float* kb, float* gb, float* vb)
{
    EpiRoute epi{bq, bk, bg, bv, qb, kb, gb, vb};
    gemm_body(A, Wall, H_DIM, blockIdx.y * 128, blockIdx.x * 128, epi);
}

// ---------------- prep: per-chunk cumulative gates ----------------
__global__ void __launch_bounds__(256) prep_kernel(
    const float* __restrict__ q, const float* __restrict__ kk,
    const float* __restrict__ g, const float* __restrict__ vv,
    float* __restrict__ qa, __half* __restrict__ qah,
    float* __restrict__ kia, float* __restrict__ a15,
    __half* __restrict__ khT, __half* __restrict__ vT)
{
    const int cid = blockIdx.x;
    const int kc = threadIdx.x * 4;
    const size_t t0 = (size_t)cid * CHUNK;
    float4 A = make_float4(1.f, 1.f, 1.f, 1.f);
#pragma unroll 4
    for (int u = 0; u < CHUNK; u++) {
        const size_t off = (t0 + u) * K_DIM + kc;
        float4 gv = *(const float4*)(g + off);
        A.x *= gv.x; A.y *= gv.y; A.z *= gv.z; A.w *= gv.w;
        float4 qv = *(const float4*)(q + off);
        float4 qa4 = make_float4(qv.x * A.x, qv.y * A.y, qv.z * A.z, qv.w * A.w);
        *(float4*)(qa + off) = qa4;
        __half2 h0 = __floats2half2_rn(qa4.x, qa4.y);
        __half2 h1 = __floats2half2_rn(qa4.z, qa4.w);
        uint2 uu; uu.x = *(unsigned*)&h0; uu.y = *(unsigned*)&h1;
        *(uint2*)(qah + off) = uu;
        float4 kv = *(const float4*)(kk + off);
        float4 ki = make_float4(__fdiv_rn(kv.x, A.x), __fdiv_rn(kv.y, A.y),
                                __fdiv_rn(kv.z, A.z), __fdiv_rn(kv.w, A.w));
        *(float4*)(kia + off) = ki;
    }
    *(float4*)(a15 + (size_t)cid * K_DIM + kc) = A;

    {
        uint32_t buf[4][16];
        float prev[4];
#pragma unroll
        for (int u = 0; u < CHUNK; u++) {
            const size_t off = (t0 + u) * K_DIM + kc;
            float4 ki = *(const float4*)(kia + off);
            float cur[4] = {ki.x * A.x, ki.y * A.y, ki.z * A.z, ki.w * A.w};
            if (u & 1) {
#pragma unroll
                for (int j = 0; j < 4; j++) {
                    __half2 h = __floats2half2_rn(prev[j], cur[j]);
                    buf[j][u >> 1] = *(unsigned*)&h;
                }
            } else {
#pragma unroll
                for (int j = 0; j < 4; j++) prev[j] = cur[j];
            }
        }
#pragma unroll
        for (int j = 0; j < 4; j++) {
            __half* dst = khT + ((size_t)cid * K_DIM + kc + j) * CHUNK;
#pragma unroll
            for (int c = 0; c < 4; c++)
                *(uint4*)(dst + c * 8) = *(uint4*)&buf[j][c * 4];
        }
    }
    {
        uint32_t buf[4][16];
        float prev[4];
#pragma unroll
        for (int u = 0; u < CHUNK; u++) {
            float4 v4 = *(const float4*)(vv + (t0 + u) * V_DIM + kc);
            float cur[4] = {v4.x, v4.y, v4.z, v4.w};
            if (u & 1) {
#pragma unroll
                for (int j = 0; j < 4; j++) {
                    __half2 h = __floats2half2_rn(prev[j], cur[j]);
                    buf[j][u >> 1] = *(unsigned*)&h;
                }
            } else {
#pragma unroll
                for (int j = 0; j < 4; j++) prev[j] = cur[j];
            }
        }
#pragma unroll
        for (int j = 0; j < 4; j++) {
            __half* dst = vT + ((size_t)cid * V_DIM + kc + j) * CHUNK;
#pragma unroll
            for (int c = 0; c < 4; c++)
                *(uint4*)(dst + c * 8) = *(uint4*)&buf[j][c * 4];
        }
    }
}

// ---------------- intra-chunk: P = QA @ KIA^T (masked), out = P @ V ----------
#define TS 128
__global__ void __launch_bounds__(256) intra_kernel(
    const float* __restrict__ qa, const float* __restrict__ kia,
    const float* __restrict__ vv, float* __restrict__ opre)
{
    __shared__ float qs[CHUNK][TS + 4];
    __shared__ float ks_[CHUNK][TS + 4];
    __shared__ float Ps[CHUNK][CHUNK + 1];
    const int tid = threadIdx.x;
    const int cid = blockIdx.x;
    const size_t t0 = (size_t)cid * CHUNK;

    for (int i = tid; i < CHUNK * (CHUNK + 1); i += 256)
        ((float*)Ps)[i] = 0.f;

    const int u0 = ((tid >> 2) & 3) * 8;
    const int s0 = (tid & 3) * 8;
    const int ksl = tid >> 4;
    float acc[8][8];
#pragma unroll
    for (int i = 0; i < 8; i++)
#pragma unroll
        for (int j = 0; j < 8; j++) acc[i][j] = 0.f;

    for (int kt = 0; kt < K_DIM; kt += TS) {
        __syncthreads();
#pragma unroll
        for (int p = 0; p < 4; p++) {
            int idx = tid + p * 256;
            int rr = idx >> 5;
            int cc = (idx & 31) * 4;
            *(float4*)&qs[rr][cc]  = *(const float4*)(qa  + (t0 + rr) * K_DIM + kt + cc);
            *(float4*)&ks_[rr][cc] = *(const float4*)(kia + (t0 + rr) * K_DIM + kt + cc);
        }
        __syncthreads();
        const int kb = ksl * 8;
#pragma unroll
        for (int km = 0; km < 8; km++) {
            const int kx = kb + km;
            float qv[8], kv[8];
#pragma unroll
            for (int i = 0; i < 8; i++) qv[i] = qs[u0 + i][kx];
#pragma unroll
            for (int j = 0; j < 8; j++) kv[j] = ks_[s0 + j][kx];
#pragma unroll
            for (int i = 0; i < 8; i++)
#pragma unroll
                for (int j = 0; j < 8; j++)
                    acc[i][j] = fmaf(qv[i], kv[j], acc[i][j]);
        }
    }
    __syncthreads();
#pragma unroll
    for (int i = 0; i < 8; i++)
#pragma unroll
        for (int j = 0; j < 8; j++)
            atomicAdd(&Ps[u0 + i][s0 + j], acc[i][j]);
    __syncthreads();

    const int vc = tid * 4;
#pragma unroll
    for (int pass = 0; pass < 4; pass++) {
        float o[8][4];
#pragma unroll
        for (int i = 0; i < 8; i++) { o[i][0] = o[i][1] = o[i][2] = o[i][3] = 0.f; }
        for (int s = 0; s < CHUNK; s++) {
            float4 v4 = *(const float4*)(vv + (t0 + s) * V_DIM + vc);
#pragma unroll
            for (int i = 0; i < 8; i++) {
                const int u = pass * 8 + i;
                float p = (s <= u) ? Ps[u][s] : 0.f;
                o[i][0] = fmaf(p, v4.x, o[i][0]);
                o[i][1] = fmaf(p, v4.y, o[i][1]);
                o[i][2] = fmaf(p, v4.z, o[i][2]);
                o[i][3] = fmaf(p, v4.w, o[i][3]);
            }
        }
#pragma unroll
        for (int i = 0; i < 8; i++) {
            const int u = pass * 8 + i;
            *(float4*)(opre + (t0 + u) * V_DIM + vc) =
                make_float4(o[i][0], o[i][1], o[i][2], o[i][3]);
        }
    }
}

// ---------------- serial v3: tensor-core state updates, 256 CTAs ------------
// 256 CTAs = 4 kg x 64 vs (16 V-cols each) -> 2 CTAs/SM for bandwidth + latency
// hiding. Warp owns 32 K-rows x 16 V-cols in mma fp32 accumulators.
__global__ void __launch_bounds__(256, 2) serial_kernel3(
    const __half* __restrict__ khT, const __half* __restrict__ vT,
    const float* __restrict__ a15, __half* __restrict__ snap,
    float* __restrict__ state_out)
{
    __shared__ __half khs[256 * KP];
    __shared__ __half vs[16 * KP];
    __shared__ __half snapS[16 * 264];
    __shared__ float a15s[256];

    const int tid = threadIdx.x;
    const int lane = tid & 31;
    const int wid = tid >> 5;
    const int kg = blockIdx.x & 3;
    const int vsb = blockIdx.x >> 2;
    const int kbaseCTA = kg * 256;
    const int vbase = vsb * 16;

    float acc[2][2][4];
#pragma unroll
    for (int mt = 0; mt < 2; mt++)
#pragma unroll
        for (int nt = 0; nt < 2; nt++)
#pragma unroll
            for (int c = 0; c < 4; c++) acc[mt][nt][c] = 0.f;

    for (int cid = 0; cid < NCHUNK; cid++) {
        // 1. snapshot acc -> snapS (fp16, [v][k], pitch 264); stage a15
#pragma unroll
        for (int mt = 0; mt < 2; mt++)
#pragma unroll
            for (int nt = 0; nt < 2; nt++)
#pragma unroll
                for (int h = 0; h < 2; h++) {
                    const int row = wid * 32 + mt * 16 + (lane >> 2) + h * 8;
                    const int col = nt * 8 + (lane & 3) * 2;
                    snapS[col * 264 + row]       = __float2half(acc[mt][nt][2 * h]);
                    snapS[(col + 1) * 264 + row] = __float2half(acc[mt][nt][2 * h + 1]);
                }
        a15s[tid] = a15[(size_t)cid * K_DIM + kbaseCTA + tid];
        __syncthreads();

        // 2. cp.async this chunk's tiles
        {
            const __half* kSrc = khT + ((size_t)cid * K_DIM + kbaseCTA) * CHUNK;
#pragma unroll
            for (int p = 0; p < 4; p++) {
                const int idx = tid + p * 256;
                const int row = idx >> 2;
                const int c = (idx & 3) * 8;
                cp_async16(&khs[row * KP + c], kSrc + row * CHUNK + c);
            }
            if (tid < 64) {
                const int row = tid >> 2;
                const int c = (tid & 3) * 8;
                cp_async16(&vs[row * KP + c],
                           vT + ((size_t)cid * V_DIM + vbase + row) * CHUNK + c);
            }
            CP_COMMIT();
        }

        // 3. snapshot -> global (coalesced 16B chunks): 16 rows x 32 chunks
        {
            const int p2 = 512;  // total chunks
            for (int idx = tid; idx < p2; idx += 256) {
                const int vr = idx >> 5;
                const int kc16 = idx & 31;
                uint4 val = *(uint4*)&snapS[vr * 264 + kc16 * 8];
                *(uint4*)(snap + ((size_t)cid * V_DIM + vbase + vr) * K_DIM +
                          kbaseCTA + kc16 * 8) = val;
            }
        }

        // 4. decay
#pragma unroll
        for (int mt = 0; mt < 2; mt++)
#pragma unroll
            for (int h = 0; h < 2; h++) {
                const float av = a15s[wid * 32 + mt * 16 + (lane >> 2) + h * 8];
#pragma unroll
                for (int nt = 0; nt < 2; nt++) {
                    acc[mt][nt][2 * h]     *= av;
                    acc[mt][nt][2 * h + 1] *= av;
                }
            }

        // 5. wait tiles; fence snapS reads before next-chunk writes
        CP_WAIT(0);
        __syncthreads();

        // 6. S += K̂^T V (2 k16 halves)
#pragma unroll
        for (int ks = 0; ks < 2; ks++) {
            const int k0 = ks * 16;
            uint32_t afr[2][4];
            uint32_t bfr[2][2];
#pragma unroll
            for (int mt = 0; mt < 2; mt++) {
                const __half* p = &khs[(wid * 32 + mt * 16 + (lane & 7) +
                                        ((lane >> 3) & 1) * 8) * KP +
                                       k0 + (lane >> 4) * 8];
                ldm_x4(afr[mt], p);
            }
            {
                uint32_t r[4];
                const __half* p = &vs[((lane & 7) + (lane >> 4) * 8) * KP +
                                      k0 + ((lane >> 3) & 1) * 8];
                ldm_x4(r, p);
                bfr[0][0] = r[0]; bfr[0][1] = r[1];
                bfr[1][0] = r[2]; bfr[1][1] = r[3];
            }
#pragma unroll
            for (int mt = 0; mt < 2; mt++)
#pragma unroll
                for (int nt = 0; nt < 2; nt++)
                    mma16816(acc[mt][nt], afr[mt], bfr[nt]);
        }
    }

    // final state (fp32, [k][v] row-major)
#pragma unroll
    for (int mt = 0; mt < 2; mt++)
#pragma unroll
        for (int nt = 0; nt < 2; nt++)
#pragma unroll
            for (int h = 0; h < 2; h++) {
                const int row = kbaseCTA + wid * 32 + mt * 16 + (lane >> 2) + h * 8;
                const int col = vbase + nt * 8 + (lane & 3) * 2;
                *(float2*)(state_out + (size_t)row * V_DIM + col) =
                    make_float2(acc[mt][nt][2 * h], acc[mt][nt][2 * h + 1]);
            }
}

// ---------------- inter: opre += qa_chunk @ snapshot^T (tensor cores) -------
__global__ void __launch_bounds__(256) inter_kernel(
    const __half* __restrict__ qah, const __half* __restrict__ snap,
    float* __restrict__ opre)
{
    __shared__ __half As[2][32 * KP];
    __shared__ __half Bs[2][128 * KP];
    const int tid = threadIdx.x;
    const int lane = tid & 31;
    const int wid = tid >> 5;
    const int warpM = wid >> 2;
    const int warpN = wid & 3;
    const int vt = blockIdx.x;
    const int cid = blockIdx.y + 1;

    const __half* A = qah + (size_t)cid * CHUNK * K_DIM;
    const __half* B = snap + ((size_t)cid * V_DIM + vt * 128) * K_DIM;

    float acc[4][4];
#pragma unroll
    for (int a = 0; a < 4; a++)
#pragma unroll
        for (int c = 0; c < 4; c++) acc[a][c] = 0.f;

#define LOAD_TILE_I(buf, k0)                                                   \
    {                                                                          \
        if (tid < 128) {                                                       \
            const int row = tid >> 2;                                          \
            const int col = (tid & 3) * 8;                                     \
            cp_async16(&As[buf][row * KP + col],                               \
                       A + (size_t)row * K_DIM + (k0) + col);                  \
        }                                                                      \
        _Pragma("unroll")                                                      \
        for (int p = 0; p < 2; p++) {                                          \
            const int c = tid + p * 256;                                       \
            const int row = c >> 2;                                            \
            const int col = (c & 3) * 8;                                       \
            cp_async16(&Bs[buf][row * KP + col],                               \
                       B + (size_t)row * K_DIM + (k0) + col);                  \
        }                                                                      \
    }

    LOAD_TILE_I(0, 0);
    CP_COMMIT();
    const int iters = K_DIM / 32;
    for (int it = 0; it < iters; ++it) {
        if (it + 1 < iters) {
            LOAD_TILE_I((it + 1) & 1, (it + 1) * 32);
            CP_COMMIT();
            CP_WAIT(1);
        } else {
            CP_WAIT(0);
        }
        __syncthreads();
        const __half* Ab = As[it & 1];
        const __half* Bb = Bs[it & 1];
#pragma unroll
        for (int ks = 0; ks < 2; ks++) {
            const int k0 = ks * 16;
            uint32_t afr[4];
            uint32_t bfr[4][2];
            {
                const __half* p = &Ab[(warpM * 16 + (lane & 7) +
                                       ((lane >> 3) & 1) * 8) * KP +
                                      k0 + (lane >> 4) * 8];
                ldm_x4(afr, p);
            }
#pragma unroll
            for (int fp = 0; fp < 2; fp++) {
                uint32_t r[4];
                const __half* p = &Bb[(warpN * 32 + fp * 16 + (lane & 7) +
                                       (lane >> 4) * 8) * KP +
                                      k0 + ((lane >> 3) & 1) * 8];
                ldm_x4(r, p);
                bfr[2 * fp][0] = r[0];     bfr[2 * fp][1] = r[1];
                bfr[2 * fp + 1][0] = r[2]; bfr[2 * fp + 1][1] = r[3];
            }
#pragma unroll
            for (int fn = 0; fn < 4; fn++) mma16816(acc[fn], afr, bfr[fn]);
        }
        __syncthreads();
    }
#undef LOAD_TILE_I

#pragma unroll
    for (int fn = 0; fn < 4; fn++)
#pragma unroll
        for (int h = 0; h < 2; h++) {
            const int row = cid * CHUNK + warpM * 16 + (lane >> 2) + h * 8;
            const int col = vt * 128 + warpN * 32 + fn * 8 + (lane & 3) * 2;
            float2 o = *(float2*)(opre + (size_t)row * V_DIM + col);
            o.x += acc[fn][2 * h];
            o.y += acc[fn][2 * h + 1];
            *(float2*)(opre + (size_t)row * V_DIM + col) = o;
        }
}

// ---------------------------------------------------------------------------
extern "C" void kernel_launch(void* const* d_in, const int* in_sizes, int n_in,
                              void* d_out, int out_size)
{
    const float* X  = (const float*)d_in[0];
    const float* Wq = (const float*)d_in[1];
    const float* bq = (const float*)d_in[2];
    const float* Wk = (const float*)d_in[3];
    const float* bk = (const float*)d_in[4];
    const float* Wv = (const float*)d_in[5];
    const float* bv = (const float*)d_in[6];
    const float* Wg = (const float*)d_in[7];
    const float* bg = (const float*)d_in[8];
    const float* Wo = (const float*)d_in[9];
    const float* bo = (const float*)d_in[10];
    float* out = (float*)d_out;

    float* scratch = 0;
    cudaGetSymbolAddress((void**)&scratch, g_scratch);
    float* qb    = scratch;
    float* kb    = qb   + (size_t)T_DIM * K_DIM;
    float* gb    = kb   + (size_t)T_DIM * K_DIM;
    float* vb    = gb   + (size_t)T_DIM * K_DIM;
    float* qa    = vb   + (size_t)T_DIM * V_DIM;
    float* kia   = qa   + (size_t)T_DIM * K_DIM;
    float* opre  = kia  + (size_t)T_DIM * K_DIM;
    float* a15   = opre + (size_t)T_DIM * V_DIM;
    float* sdump = a15  + (size_t)NCHUNK * K_DIM;

    __half* hscr = 0;
    cudaGetSymbolAddress((void**)&hscr, g_scratch_h);
    __half* Xh    = hscr;
    __half* Wallh = Xh    + (size_t)T_DIM * H_DIM;   // [Wq;Wk;Wg;Wv] stacked
    __half* Woh   = Wallh + (size_t)4 * K_DIM * H_DIM;
    __half* opreh = Woh   + (size_t)O_DIM * V_DIM;
    __half* qah   = opreh + (size_t)T_DIM * V_DIM;
    __half* khT   = qah   + (size_t)T_DIM * K_DIM;
    __half* vT    = khT   + (size_t)T_DIM * K_DIM;
    __half* snap  = vT    + (size_t)T_DIM * K_DIM;

    const size_t out_main = (size_t)T_DIM * O_DIM;
    const size_t out_full = out_main + (size_t)K_DIM * V_DIM;
    float* state_out = ((size_t)out_size >= out_full) ? (out + out_main) : sdump;

    dim3 blk(256);

    // fp32->fp16 conversions: X, [Wq|Wk|Wg|Wv] batched, Wo
    f2h_kernel<<<2048, 256>>>(X, Xh, (int)((size_t)T_DIM * H_DIM / 4));
    f2h4_kernel<<<dim3(512, 4), 256>>>(Wq, Wk, Wg, Wv, Wallh,
                                       (int)((size_t)K_DIM * H_DIM / 4));
    f2h_kernel<<<1024, 256>>>(Wo, Woh, (int)((size_t)O_DIM * V_DIM / 4));

    // merged projection GEMM: one launch, routed epilogue
    gemm_h_nt_proj<<<dim3(4 * K_DIM / 128, T_DIM / 128), blk>>>(
        Xh, Wallh, bq, bk, bg, bv, qb, kb, gb, vb);

    // chunked gated-linear-attention pipeline
    prep_kernel<<<NCHUNK, blk>>>(qb, kb, gb, vb, qa, qah, kia, a15, khT, vT);
    intra_kernel<<<NCHUNK, blk>>>(qa, kia, vb, opre);
    serial_kernel3<<<256, blk>>>(khT, vT, a15, snap, state_out);
    inter_kernel<<<dim3(8, NCHUNK - 1), blk>>>(qah, snap, opre);

    // opre -> fp16, output projection
    f2h_kernel<<<1024, 256>>>(opre, opreh, (int)((size_t)T_DIM * V_DIM / 4));
    gemm_h_nt<<<dim3(O_DIM / 128, T_DIM / 128), blk>>>(opreh, Woh, bo, out,
                                                       T_DIM, O_DIM, V_DIM, 0);
}

// round 13
// speedup vs baseline: 3.4248x; 1.0537x over previous
#include <cuda_runtime.h>
#include <cuda_fp16.h>
#include <math.h>
#include <stddef.h>
#include <stdint.h>

typedef unsigned long long ull;

#define T_DIM 4096
#define H_DIM 2048
#define K_DIM 1024
#define V_DIM 1024
#define O_DIM 2048
#define CHUNK 32
#define NCHUNK 128

// fp32 scratch: q | k | g | v | qa | kia | opre | a15 | sdump
__device__ __align__(16) float g_scratch[(size_t)5 * T_DIM * K_DIM +
                                         (size_t)2 * T_DIM * V_DIM +
                                         (size_t)NCHUNK * K_DIM +
                                         (size_t)K_DIM * V_DIM];
// fp16 scratch: Xh | Wall | Woh | opreh | qah | khT | vT | snap
__device__ __align__(16) __half g_scratch_h[(size_t)T_DIM * H_DIM +
                                            (size_t)4 * K_DIM * H_DIM +
                                            (size_t)O_DIM * V_DIM +
                                            (size_t)T_DIM * V_DIM +
                                            (size_t)3 * T_DIM * K_DIM +
                                            (size_t)NCHUNK * K_DIM * V_DIM];

// ---------------- helpers ----------------
__device__ __forceinline__ uint32_t smem_u32(const void* p) {
    return (uint32_t)__cvta_generic_to_shared(p);
}
__device__ __forceinline__ void ldm_x4(uint32_t* r, const __half* p) {
    uint32_t addr = smem_u32(p);
    asm volatile("ldmatrix.sync.aligned.m8n8.x4.shared.b16 {%0,%1,%2,%3}, [%4];"
                 : "=r"(r[0]), "=r"(r[1]), "=r"(r[2]), "=r"(r[3]) : "r"(addr));
}
__device__ __forceinline__ void mma16816(float* d, const uint32_t* a, const uint32_t* b) {
    asm volatile(
        "mma.sync.aligned.m16n8k16.row.col.f32.f16.f16.f32 "
        "{%0,%1,%2,%3}, {%4,%5,%6,%7}, {%8,%9}, {%0,%1,%2,%3};"
        : "+f"(d[0]), "+f"(d[1]), "+f"(d[2]), "+f"(d[3])
        : "r"(a[0]), "r"(a[1]), "r"(a[2]), "r"(a[3]), "r"(b[0]), "r"(b[1]));
}
__device__ __forceinline__ void cp_async16(__half* smem_dst, const __half* gsrc) {
    asm volatile("cp.async.cg.shared.global [%0], [%1], 16;"
                 :: "r"(smem_u32(smem_dst)), "l"(gsrc));
}
__device__ __forceinline__ void cp_async16_g(void* smem_dst, const void* gsrc) {
    asm volatile("cp.async.cg.shared.global [%0], [%1], 16;"
                 :: "r"(smem_u32(smem_dst)), "l"(gsrc));
}
#define CP_COMMIT() asm volatile("cp.async.commit_group;")
#define CP_WAIT(n)  asm volatile("cp.async.wait_group %0;" :: "n"(n))

// ---------------- fp32 -> fp16 convert (single + batched x4) ----------------
__global__ void f2h_kernel(const float* __restrict__ src, __half* __restrict__ dst, int n4)
{
    int i = blockIdx.x * blockDim.x + threadIdx.x;
    const int stride = gridDim.x * blockDim.x;
    for (; i < n4; i += stride) {
        float4 v = ((const float4*)src)[i];
        __half2 h0 = __floats2half2_rn(v.x, v.y);
        __half2 h1 = __floats2half2_rn(v.z, v.w);
        uint2 u;
        u.x = *reinterpret_cast<unsigned*>(&h0);
        u.y = *reinterpret_cast<unsigned*>(&h1);
        ((uint2*)dst)[i] = u;
    }
}
__global__ void f2h4_kernel(const float* __restrict__ s0, const float* __restrict__ s1,
                            const float* __restrict__ s2, const float* __restrict__ s3,
                            __half* __restrict__ dst, int n4)
{
    const float* src = (blockIdx.y == 0) ? s0 : (blockIdx.y == 1) ? s1
                       : (blockIdx.y == 2) ? s2 : s3;
    __half* d = dst + (size_t)blockIdx.y * (size_t)n4 * 4;
    int i = blockIdx.x * blockDim.x + threadIdx.x;
    const int stride = gridDim.x * blockDim.x;
    for (; i < n4; i += stride) {
        float4 v = ((const float4*)src)[i];
        __half2 h0 = __floats2half2_rn(v.x, v.y);
        __half2 h1 = __floats2half2_rn(v.z, v.w);
        uint2 u;
        u.x = *reinterpret_cast<unsigned*>(&h0);
        u.y = *reinterpret_cast<unsigned*>(&h1);
        ((uint2*)d)[i] = u;
    }
}

// ---------------- fp16 NT GEMM core (proven R10) ----------------------------
#define KP 40
struct EpiPlain {
    const float* bias; float* C; int N; int act;
    __device__ __forceinline__ void store(int row, int col, float c0, float c1) const {
        c0 += __ldg(&bias[col]); c1 += __ldg(&bias[col + 1]);
        if (act) { c0 = 1.f / (1.f + expf(-c0)); c1 = 1.f / (1.f + expf(-c1)); }
        *(float2*)(C + (size_t)row * N + col) = make_float2(c0, c1);
    }
};
// routed epilogue: col>>10 selects one of 4 outputs (k,g get sigmoid)
struct EpiRoute {
    const float* b0; const float* b1; const float* b2; const float* b3;
    float* d0; float* d1; float* d2; float* d3;
    __device__ __forceinline__ void store(int row, int col, float c0, float c1) const {
        const int sel = col >> 10;
        const int lc = col & 1023;
        const float* bias = (sel == 0) ? b0 : (sel == 1) ? b1 : (sel == 2) ? b2 : b3;
        float* C = (sel == 0) ? d0 : (sel == 1) ? d1 : (sel == 2) ? d2 : d3;
        c0 += __ldg(&bias[lc]); c1 += __ldg(&bias[lc + 1]);
        if (sel == 1 || sel == 2) {
            c0 = 1.f / (1.f + expf(-c0)); c1 = 1.f / (1.f + expf(-c1));
        }
        *(float2*)(C + (size_t)row * 1024 + lc) = make_float2(c0, c1);
    }
};

template <class Epi>
__device__ __forceinline__ void gemm_body(
    const __half* __restrict__ A, const __half* __restrict__ B,
    int Kd, int bm, int bn, const Epi& epi)
{
    __shared__ __half As[2][128 * KP];
    __shared__ __half Bs[2][128 * KP];

    const int tid = threadIdx.x;
    const int lane = tid & 31;
    const int wid = tid >> 5;
    const int warpM = wid >> 2;
    const int warpN = wid & 3;

    float acc[4][4][4];
#pragma unroll
    for (int a = 0; a < 4; a++)
#pragma unroll
        for (int b = 0; b < 4; b++)
#pragma unroll
            for (int c = 0; c < 4; c++) acc[a][b][c] = 0.f;

    const int iters = Kd / 32;

#define LOAD_TILE(buf, k0)                                                     \
    {                                                                          \
        _Pragma("unroll")                                                      \
        for (int p = 0; p < 2; p++) {                                          \
            const int c = tid + p * 256;                                       \
            const int row = c >> 2;                                            \
            const int col = (c & 3) * 8;                                       \
            cp_async16(&As[buf][row * KP + col],                               \
                       A + (size_t)(bm + row) * Kd + (k0) + col);              \
            cp_async16(&Bs[buf][row * KP + col],                               \
                       B + (size_t)(bn + row) * Kd + (k0) + col);              \
        }                                                                      \
    }

    LOAD_TILE(0, 0);
    CP_COMMIT();

    for (int it = 0; it < iters; ++it) {
        if (it + 1 < iters) {
            LOAD_TILE((it + 1) & 1, (it + 1) * 32);
            CP_COMMIT();
            CP_WAIT(1);
        } else {
            CP_WAIT(0);
        }
        __syncthreads();

        const __half* Ab = As[it & 1];
        const __half* Bb = Bs[it & 1];
#pragma unroll
        for (int ks = 0; ks < 2; ks++) {
            const int k0 = ks * 16;
            uint32_t afr[4][4];
            uint32_t bfr[4][2];
#pragma unroll
            for (int fm = 0; fm < 4; fm++) {
                const __half* p = &Ab[(warpM * 64 + fm * 16 + (lane & 7) +
                                       ((lane >> 3) & 1) * 8) * KP +
                                      k0 + (lane >> 4) * 8];
                ldm_x4(afr[fm], p);
            }
#pragma unroll
            for (int fp = 0; fp < 2; fp++) {
                uint32_t r[4];
                const __half* p = &Bb[(warpN * 32 + fp * 16 + (lane & 7) +
                                       (lane >> 4) * 8) * KP +
                                      k0 + ((lane >> 3) & 1) * 8];
                ldm_x4(r, p);
                bfr[2 * fp][0] = r[0];     bfr[2 * fp][1] = r[1];
                bfr[2 * fp + 1][0] = r[2]; bfr[2 * fp + 1][1] = r[3];
            }
#pragma unroll
            for (int fm = 0; fm < 4; fm++)
#pragma unroll
                for (int fn = 0; fn < 4; fn++)
                    mma16816(acc[fm][fn], afr[fm], bfr[fn]);
        }
        __syncthreads();
    }
#undef LOAD_TILE

#pragma unroll
    for (int fm = 0; fm < 4; fm++)
#pragma unroll
        for (int fn = 0; fn < 4; fn++)
#pragma unroll
            for (int h = 0; h < 2; h++) {
                const int row = bm + warpM * 64 + fm * 16 + (lane >> 2) + h * 8;
                const int col = bn + warpN * 32 + fn * 8 + (lane & 3) * 2;
                epi.store(row, col, acc[fm][fn][2 * h], acc[fm][fn][2 * h + 1]);
            }
}

__global__ void __launch_bounds__(256, 2) gemm_h_nt(
    const __half* __restrict__ A, const __half* __restrict__ B,
    const float* __restrict__ bias, float* __restrict__ C,
    int M, int N, int Kd, int act)
{
    EpiPlain epi{bias, C, N, act};
    gemm_body(A, B, Kd, blockIdx.y * 128, blockIdx.x * 128, epi);
}

// merged 4-projection GEMM: B = stacked [Wq;Wk;Wg;Wv] (4096 x 2048), routed epi
__global__ void __launch_bounds__(256, 2) gemm_h_nt_proj(
    const __half* __restrict__ A, const __half* __restrict__ Wall,
    const float* bq, const float* bk, const float* bg, const float* bv,
    float* qb, float* kb, float* gb, float* vb)
{
    EpiRoute epi{bq, bk, bg, bv, qb, kb, gb, vb};
    gemm_body(A, Wall, H_DIM, blockIdx.y * 128, blockIdx.x * 128, epi);
}

// ---------------- prep: per-chunk cumulative gates ----------------
__global__ void __launch_bounds__(256) prep_kernel(
    const float* __restrict__ q, const float* __restrict__ kk,
    const float* __restrict__ g, const float* __restrict__ vv,
    float* __restrict__ qa, __half* __restrict__ qah,
    float* __restrict__ kia, float* __restrict__ a15,
    __half* __restrict__ khT, __half* __restrict__ vT)
{
    const int cid = blockIdx.x;
    const int kc = threadIdx.x * 4;
    const size_t t0 = (size_t)cid * CHUNK;
    float4 A = make_float4(1.f, 1.f, 1.f, 1.f);
#pragma unroll 4
    for (int u = 0; u < CHUNK; u++) {
        const size_t off = (t0 + u) * K_DIM + kc;
        float4 gv = *(const float4*)(g + off);
        A.x *= gv.x; A.y *= gv.y; A.z *= gv.z; A.w *= gv.w;
        float4 qv = *(const float4*)(q + off);
        float4 qa4 = make_float4(qv.x * A.x, qv.y * A.y, qv.z * A.z, qv.w * A.w);
        *(float4*)(qa + off) = qa4;
        __half2 h0 = __floats2half2_rn(qa4.x, qa4.y);
        __half2 h1 = __floats2half2_rn(qa4.z, qa4.w);
        uint2 uu; uu.x = *(unsigned*)&h0; uu.y = *(unsigned*)&h1;
        *(uint2*)(qah + off) = uu;
        float4 kv = *(const float4*)(kk + off);
        float4 ki = make_float4(__fdiv_rn(kv.x, A.x), __fdiv_rn(kv.y, A.y),
                                __fdiv_rn(kv.z, A.z), __fdiv_rn(kv.w, A.w));
        *(float4*)(kia + off) = ki;
    }
    *(float4*)(a15 + (size_t)cid * K_DIM + kc) = A;

    {
        uint32_t buf[4][16];
        float prev[4];
#pragma unroll
        for (int u = 0; u < CHUNK; u++) {
            const size_t off = (t0 + u) * K_DIM + kc;
            float4 ki = *(const float4*)(kia + off);
            float cur[4] = {ki.x * A.x, ki.y * A.y, ki.z * A.z, ki.w * A.w};
            if (u & 1) {
#pragma unroll
                for (int j = 0; j < 4; j++) {
                    __half2 h = __floats2half2_rn(prev[j], cur[j]);
                    buf[j][u >> 1] = *(unsigned*)&h;
                }
            } else {
#pragma unroll
                for (int j = 0; j < 4; j++) prev[j] = cur[j];
            }
        }
#pragma unroll
        for (int j = 0; j < 4; j++) {
            __half* dst = khT + ((size_t)cid * K_DIM + kc + j) * CHUNK;
#pragma unroll
            for (int c = 0; c < 4; c++)
                *(uint4*)(dst + c * 8) = *(uint4*)&buf[j][c * 4];
        }
    }
    {
        uint32_t buf[4][16];
        float prev[4];
#pragma unroll
        for (int u = 0; u < CHUNK; u++) {
            float4 v4 = *(const float4*)(vv + (t0 + u) * V_DIM + kc);
            float cur[4] = {v4.x, v4.y, v4.z, v4.w};
            if (u & 1) {
#pragma unroll
                for (int j = 0; j < 4; j++) {
                    __half2 h = __floats2half2_rn(prev[j], cur[j]);
                    buf[j][u >> 1] = *(unsigned*)&h;
                }
            } else {
#pragma unroll
                for (int j = 0; j < 4; j++) prev[j] = cur[j];
            }
        }
#pragma unroll
        for (int j = 0; j < 4; j++) {
            __half* dst = vT + ((size_t)cid * V_DIM + kc + j) * CHUNK;
#pragma unroll
            for (int c = 0; c < 4; c++)
                *(uint4*)(dst + c * 8) = *(uint4*)&buf[j][c * 4];
        }
    }
}

// ---------------- intra-chunk: P = QA @ KIA^T (masked), out = P @ V ----------
#define TS 128
__global__ void __launch_bounds__(256) intra_kernel(
    const float* __restrict__ qa, const float* __restrict__ kia,
    const float* __restrict__ vv, float* __restrict__ opre)
{
    __shared__ float qs[CHUNK][TS + 4];
    __shared__ float ks_[CHUNK][TS + 4];
    __shared__ float Ps[CHUNK][CHUNK + 1];
    const int tid = threadIdx.x;
    const int cid = blockIdx.x;
    const size_t t0 = (size_t)cid * CHUNK;

    for (int i = tid; i < CHUNK * (CHUNK + 1); i += 256)
        ((float*)Ps)[i] = 0.f;

    const int u0 = ((tid >> 2) & 3) * 8;
    const int s0 = (tid & 3) * 8;
    const int ksl = tid >> 4;
    float acc[8][8];
#pragma unroll
    for (int i = 0; i < 8; i++)
#pragma unroll
        for (int j = 0; j < 8; j++) acc[i][j] = 0.f;

    for (int kt = 0; kt < K_DIM; kt += TS) {
        __syncthreads();
#pragma unroll
        for (int p = 0; p < 4; p++) {
            int idx = tid + p * 256;
            int rr = idx >> 5;
            int cc = (idx & 31) * 4;
            *(float4*)&qs[rr][cc]  = *(const float4*)(qa  + (t0 + rr) * K_DIM + kt + cc);
            *(float4*)&ks_[rr][cc] = *(const float4*)(kia + (t0 + rr) * K_DIM + kt + cc);
        }
        __syncthreads();
        const int kb = ksl * 8;
#pragma unroll
        for (int km = 0; km < 8; km++) {
            const int kx = kb + km;
            float qv[8], kv[8];
#pragma unroll
            for (int i = 0; i < 8; i++) qv[i] = qs[u0 + i][kx];
#pragma unroll
            for (int j = 0; j < 8; j++) kv[j] = ks_[s0 + j][kx];
#pragma unroll
            for (int i = 0; i < 8; i++)
#pragma unroll
                for (int j = 0; j < 8; j++)
                    acc[i][j] = fmaf(qv[i], kv[j], acc[i][j]);
        }
    }
    __syncthreads();
#pragma unroll
    for (int i = 0; i < 8; i++)
#pragma unroll
        for (int j = 0; j < 8; j++)
            atomicAdd(&Ps[u0 + i][s0 + j], acc[i][j]);
    __syncthreads();

    const int vc = tid * 4;
#pragma unroll
    for (int pass = 0; pass < 4; pass++) {
        float o[8][4];
#pragma unroll
        for (int i = 0; i < 8; i++) { o[i][0] = o[i][1] = o[i][2] = o[i][3] = 0.f; }
        for (int s = 0; s < CHUNK; s++) {
            float4 v4 = *(const float4*)(vv + (t0 + s) * V_DIM + vc);
#pragma unroll
            for (int i = 0; i < 8; i++) {
                const int u = pass * 8 + i;
                float p = (s <= u) ? Ps[u][s] : 0.f;
                o[i][0] = fmaf(p, v4.x, o[i][0]);
                o[i][1] = fmaf(p, v4.y, o[i][1]);
                o[i][2] = fmaf(p, v4.z, o[i][2]);
                o[i][3] = fmaf(p, v4.w, o[i][3]);
            }
        }
#pragma unroll
        for (int i = 0; i < 8; i++) {
            const int u = pass * 8 + i;
            *(float4*)(opre + (t0 + u) * V_DIM + vc) =
                make_float4(o[i][0], o[i][1], o[i][2], o[i][3]);
        }
    }
}

// ---------------- serial v4: double-buffered tensor-core state updates ------
// 256 CTAs = 4 kg x 64 vs (16 V-cols); warp owns 32 K-rows x 16 V-cols in mma
// fp32 accumulators. NEW vs v3: chunk cid+1's khT/vT/a15 tiles are prefetched
// into a second smem buffer while chunk cid computes -> the cp.async latency
// (previously exposed on the 128-long serial chain) is hidden.
// Dynamic smem layout (bytes):
//   khs[2]  @ 0      : 2 x 256*KP*2 = 40960
//   vs[2]   @ 40960  : 2 x 16*KP*2  = 2560
//   a15s[2] @ 43520  : 2 x 1024     = 2048
//   snapS   @ 45568  : 16*264*2     = 8448     total 54016
#define SER_DSMEM 54016
__global__ void __launch_bounds__(256, 2) serial_kernel4(
    const __half* __restrict__ khT, const __half* __restrict__ vT,
    const float* __restrict__ a15, __half* __restrict__ snap,
    float* __restrict__ state_out)
{
    extern __shared__ char dyn[];
    __half* khsA[2] = {(__half*)(dyn),         (__half*)(dyn + 20480)};
    __half* vsA[2]  = {(__half*)(dyn + 40960), (__half*)(dyn + 42240)};
    float*  a15A[2] = {(float*)(dyn + 43520),  (float*)(dyn + 44544)};
    __half* snapS   = (__half*)(dyn + 45568);

    const int tid = threadIdx.x;
    const int lane = tid & 31;
    const int wid = tid >> 5;
    const int kg = blockIdx.x & 3;
    const int vsb = blockIdx.x >> 2;
    const int kbaseCTA = kg * 256;
    const int vbase = vsb * 16;

    // prefetch macro: chunk c -> buffer b (khs 1024x16B, vs 64x16B, a15 64x16B)
#define SER_PREF(c, b)                                                         \
    {                                                                          \
        const __half* kSrc = khT + ((size_t)(c) * K_DIM + kbaseCTA) * CHUNK;   \
        _Pragma("unroll")                                                      \
        for (int p = 0; p < 4; p++) {                                          \
            const int idx = tid + p * 256;                                     \
            const int row = idx >> 2;                                          \
            const int cc = (idx & 3) * 8;                                      \
            cp_async16(&khsA[b][row * KP + cc], kSrc + row * CHUNK + cc);      \
        }                                                                      \
        if (tid < 64) {                                                        \
            const int row = tid >> 2;                                          \
            const int cc = (tid & 3) * 8;                                      \
            cp_async16(&vsA[b][row * KP + cc],                                 \
                       vT + ((size_t)(c) * V_DIM + vbase + row) * CHUNK + cc); \
        } else if (tid < 128) {                                                \
            const int j = tid - 64;                                            \
            cp_async16_g(&a15A[b][j * 4],                                      \
                         a15 + (size_t)(c) * K_DIM + kbaseCTA + j * 4);        \
        }                                                                      \
        CP_COMMIT();                                                           \
    }

    float acc[2][2][4];
#pragma unroll
    for (int mt = 0; mt < 2; mt++)
#pragma unroll
        for (int nt = 0; nt < 2; nt++)
#pragma unroll
            for (int c = 0; c < 4; c++) acc[mt][nt][c] = 0.f;

    SER_PREF(0, 0);   // group 0

    for (int cid = 0; cid < NCHUNK; cid++) {
        const int buf = cid & 1;

        // 1. snapshot PRE-update acc -> snapS (fp16, [v][k], pitch 264)
#pragma unroll
        for (int mt = 0; mt < 2; mt++)
#pragma unroll
            for (int nt = 0; nt < 2; nt++)
#pragma unroll
                for (int h = 0; h < 2; h++) {
                    const int row = wid * 32 + mt * 16 + (lane >> 2) + h * 8;
                    const int col = nt * 8 + (lane & 3) * 2;
                    snapS[col * 264 + row]       = __float2half(acc[mt][nt][2 * h]);
                    snapS[(col + 1) * 264 + row] = __float2half(acc[mt][nt][2 * h + 1]);
                }
        __syncthreads();   // publishes snapS; closes prev iter's ldm reads of buf^1

        // 2. prefetch next chunk into the other buffer (safe: reads closed)
        if (cid + 1 < NCHUNK) SER_PREF(cid + 1, buf ^ 1);

        // 3. snapshot -> global (coalesced 16B chunks)
        for (int idx = tid; idx < 512; idx += 256) {
            const int vr = idx >> 5;
            const int kc16 = idx & 31;
            uint4 val = *(uint4*)&snapS[vr * 264 + kc16 * 8];
            *(uint4*)(snap + ((size_t)cid * V_DIM + vbase + vr) * K_DIM +
                      kbaseCTA + kc16 * 8) = val;
        }

        // 4. wait for THIS chunk's tiles (issued last iteration) + visibility
        if (cid + 1 < NCHUNK) { CP_WAIT(1); } else { CP_WAIT(0); }
        __syncthreads();

        // 5. decay by a15 (from prefetched smem)
#pragma unroll
        for (int mt = 0; mt < 2; mt++)
#pragma unroll
            for (int h = 0; h < 2; h++) {
                const float av = a15A[buf][wid * 32 + mt * 16 + (lane >> 2) + h * 8];
#pragma unroll
                for (int nt = 0; nt < 2; nt++) {
                    acc[mt][nt][2 * h]     *= av;
                    acc[mt][nt][2 * h + 1] *= av;
                }
            }

        // 6. S += K̂^T V (2 k16 halves)
#pragma unroll
        for (int ks = 0; ks < 2; ks++) {
            const int k0 = ks * 16;
            uint32_t afr[2][4];
            uint32_t bfr[2][2];
#pragma unroll
            for (int mt = 0; mt < 2; mt++) {
                const __half* p = &khsA[buf][(wid * 32 + mt * 16 + (lane & 7) +
                                              ((lane >> 3) & 1) * 8) * KP +
                                             k0 + (lane >> 4) * 8];
                ldm_x4(afr[mt], p);
            }
            {
                uint32_t r[4];
                const __half* p = &vsA[buf][((lane & 7) + (lane >> 4) * 8) * KP +
                                            k0 + ((lane >> 3) & 1) * 8];
                ldm_x4(r, p);
                bfr[0][0] = r[0]; bfr[0][1] = r[1];
                bfr[1][0] = r[2]; bfr[1][1] = r[3];
            }
#pragma unroll
            for (int mt = 0; mt < 2; mt++)
#pragma unroll
                for (int nt = 0; nt < 2; nt++)
                    mma16816(acc[mt][nt], afr[mt], bfr[nt]);
        }
    }
#undef SER_PREF

    // final state (fp32, [k][v] row-major)
#pragma unroll
    for (int mt = 0; mt < 2; mt++)
#pragma unroll
        for (int nt = 0; nt < 2; nt++)
#pragma unroll
            for (int h = 0; h < 2; h++) {
                const int row = kbaseCTA + wid * 32 + mt * 16 + (lane >> 2) + h * 8;
                const int col = vbase + nt * 8 + (lane & 3) * 2;
                *(float2*)(state_out + (size_t)row * V_DIM + col) =
                    make_float2(acc[mt][nt][2 * h], acc[mt][nt][2 * h + 1]);
            }
}

// ---------------- inter: opre += qa_chunk @ snapshot^T (mma.sync) -----------
__global__ void __launch_bounds__(256) inter_kernel(
    const __half* __restrict__ qah, const __half* __restrict__ snap,
    float* __restrict__ opre)
{
    __shared__ __half As[2][32 * KP];
    __shared__ __half Bs[2][128 * KP];
    const int tid = threadIdx.x;
    const int lane = tid & 31;
    const int wid = tid >> 5;
    const int warpM = wid >> 2;
    const int warpN = wid & 3;
    const int vt = blockIdx.x;
    const int cid = blockIdx.y + 1;

    const __half* A = qah + (size_t)cid * CHUNK * K_DIM;
    const __half* B = snap + ((size_t)cid * V_DIM + vt * 128) * K_DIM;

    float acc[4][4];
#pragma unroll
    for (int a = 0; a < 4; a++)
#pragma unroll
        for (int c = 0; c < 4; c++) acc[a][c] = 0.f;

#define LOAD_TILE_I(buf, k0)                                                   \
    {                                                                          \
        if (tid < 128) {                                                       \
            const int row = tid >> 2;                                          \
            const int col = (tid & 3) * 8;                                     \
            cp_async16(&As[buf][row * KP + col],                               \
                       A + (size_t)row * K_DIM + (k0) + col);                  \
        }                                                                      \
        _Pragma("unroll")                                                      \
        for (int p = 0; p < 2; p++) {                                          \
            const int c = tid + p * 256;                                       \
            const int row = c >> 2;                                            \
            const int col = (c & 3) * 8;                                       \
            cp_async16(&Bs[buf][row * KP + col],                               \
                       B + (size_t)row * K_DIM + (k0) + col);                  \
        }                                                                      \
    }

    LOAD_TILE_I(0, 0);
    CP_COMMIT();
    const int iters = K_DIM / 32;
    for (int it = 0; it < iters; ++it) {
        if (it + 1 < iters) {
            LOAD_TILE_I((it + 1) & 1, (it + 1) * 32);
            CP_COMMIT();
            CP_WAIT(1);
        } else {
            CP_WAIT(0);
        }
        __syncthreads();
        const __half* Ab = As[it & 1];
        const __half* Bb = Bs[it & 1];
#pragma unroll
        for (int ks = 0; ks < 2; ks++) {
            const int k0 = ks * 16;
            uint32_t afr[4];
            uint32_t bfr[4][2];
            {
                const __half* p = &Ab[(warpM * 16 + (lane & 7) +
                                       ((lane >> 3) & 1) * 8) * KP +
                                      k0 + (lane >> 4) * 8];
                ldm_x4(afr, p);
            }
#pragma unroll
            for (int fp = 0; fp < 2; fp++) {
                uint32_t r[4];
                const __half* p = &Bb[(warpN * 32 + fp * 16 + (lane & 7) +
                                       (lane >> 4) * 8) * KP +
                                      k0 + ((lane >> 3) & 1) * 8];
                ldm_x4(r, p);
                bfr[2 * fp][0] = r[0];     bfr[2 * fp][1] = r[1];
                bfr[2 * fp + 1][0] = r[2]; bfr[2 * fp + 1][1] = r[3];
            }
#pragma unroll
            for (int fn = 0; fn < 4; fn++) mma16816(acc[fn], afr, bfr[fn]);
        }
        __syncthreads();
    }
#undef LOAD_TILE_I

#pragma unroll
    for (int fn = 0; fn < 4; fn++)
#pragma unroll
        for (int h = 0; h < 2; h++) {
            const int row = cid * CHUNK + warpM * 16 + (lane >> 2) + h * 8;
            const int col = vt * 128 + warpN * 32 + fn * 8 + (lane & 3) * 2;
            float2 o = *(float2*)(opre + (size_t)row * V_DIM + col);
            o.x += acc[fn][2 * h];
            o.y += acc[fn][2 * h + 1];
            *(float2*)(opre + (size_t)row * V_DIM + col) = o;
        }
}

// ---------------------------------------------------------------------------
extern "C" void kernel_launch(void* const* d_in, const int* in_sizes, int n_in,
                              void* d_out, int out_size)
{
    const float* X  = (const float*)d_in[0];
    const float* Wq = (const float*)d_in[1];
    const float* bq = (const float*)d_in[2];
    const float* Wk = (const float*)d_in[3];
    const float* bk = (const float*)d_in[4];
    const float* Wv = (const float*)d_in[5];
    const float* bv = (const float*)d_in[6];
    const float* Wg = (const float*)d_in[7];
    const float* bg = (const float*)d_in[8];
    const float* Wo = (const float*)d_in[9];
    const float* bo = (const float*)d_in[10];
    float* out = (float*)d_out;

    float* scratch = 0;
    cudaGetSymbolAddress((void**)&scratch, g_scratch);
    float* qb    = scratch;
    float* kb    = qb   + (size_t)T_DIM * K_DIM;
    float* gb    = kb   + (size_t)T_DIM * K_DIM;
    float* vb    = gb   + (size_t)T_DIM * K_DIM;
    float* qa    = vb   + (size_t)T_DIM * V_DIM;
    float* kia   = qa   + (size_t)T_DIM * K_DIM;
    float* opre  = kia  + (size_t)T_DIM * K_DIM;
    float* a15   = opre + (size_t)T_DIM * V_DIM;
    float* sdump = a15  + (size_t)NCHUNK * K_DIM;

    __half* hscr = 0;
    cudaGetSymbolAddress((void**)&hscr, g_scratch_h);
    __half* Xh    = hscr;
    __half* Wallh = Xh    + (size_t)T_DIM * H_DIM;
    __half* Woh   = Wallh + (size_t)4 * K_DIM * H_DIM;
    __half* opreh = Woh   + (size_t)O_DIM * V_DIM;
    __half* qah   = opreh + (size_t)T_DIM * V_DIM;
    __half* khT   = qah   + (size_t)T_DIM * K_DIM;
    __half* vT    = khT   + (size_t)T_DIM * K_DIM;
    __half* snap  = vT    + (size_t)T_DIM * K_DIM;

    const size_t out_main = (size_t)T_DIM * O_DIM;
    const size_t out_full = out_main + (size_t)K_DIM * V_DIM;
    float* state_out = ((size_t)out_size >= out_full) ? (out + out_main) : sdump;

    // opt-in dynamic smem for the double-buffered serial kernel (host API only)
    cudaFuncSetAttribute(serial_kernel4, cudaFuncAttributeMaxDynamicSharedMemorySize,
                         SER_DSMEM);

    dim3 blk(256);

    f2h_kernel<<<2048, 256>>>(X, Xh, (int)((size_t)T_DIM * H_DIM / 4));
    f2h4_kernel<<<dim3(512, 4), 256>>>(Wq, Wk, Wg, Wv, Wallh,
                                       (int)((size_t)K_DIM * H_DIM / 4));
    f2h_kernel<<<1024, 256>>>(Wo, Woh, (int)((size_t)O_DIM * V_DIM / 4));

    // merged projection GEMM: one launch, routed epilogue
    gemm_h_nt_proj<<<dim3(4 * K_DIM / 128, T_DIM / 128), blk>>>(
        Xh, Wallh, bq, bk, bg, bv, qb, kb, gb, vb);

    // chunked gated-linear-attention pipeline
    prep_kernel<<<NCHUNK, blk>>>(qb, kb, gb, vb, qa, qah, kia, a15, khT, vT);
    intra_kernel<<<NCHUNK, blk>>>(qa, kia, vb, opre);
    serial_kernel4<<<256, blk, SER_DSMEM>>>(khT, vT, a15, snap, state_out);
    inter_kernel<<<dim3(8, NCHUNK - 1), blk>>>(qah, snap, opre);

    // opre -> fp16, output projection
    f2h_kernel<<<1024, 256>>>(opre, opreh, (int)((size_t)T_DIM * V_DIM / 4));
    gemm_h_nt<<<dim3(O_DIM / 128, T_DIM / 128), blk>>>(opreh, Woh, bo, out,
                                                       T_DIM, O_DIM, V_DIM, 0);
}